// round 5
// baseline (speedup 1.0000x reference)
#include <cuda_runtime.h>
#include <math.h>

#define NB 512
#define NT 64
#define NS 30
#define ND 200
#define NH 200
#define NA 12
#define NE 1024
#define OUTC 380
#define R 4

typedef unsigned long long ull;

// ---------------- device-global scratch (allocation-free rule) ----------------
// Pre-DUPLICATED fp32 weights: each component stored as an adjacent (w,w) pair
// so loads produce ready-to-use f32x2 operands with zero MOVs.
__device__ __align__(16) float4 g_rc4[400 * 200];  // (w_r, w_r, w_c, w_c) at [k][u]
__device__ __align__(16) float2 g_uw2[400 * 200];  // (w_u, w_u)          at [k][u]
__device__ __align__(16) float4 g_io4[200 * 200];  // (w_img, w_img, w_obs, w_obs) at [k][j]
__device__ __align__(16) float4 g_ef4[200 * 60];   // (w_ims, w_ims, w_obs, w_obs) at [k][u]
__device__ __align__(16) float2 g_in2[30 * 200];   // (w_inp, w_inp) at [k][j]
__device__ float g_pre_inp[NB * NT * NH];
__device__ float g_pre_obs[NB * NT * NH];

// ---------------- packed f32x2 helpers ----------------
__device__ __forceinline__ ull pack2(float lo, float hi) {
    ull r; asm("mov.b64 %0, {%1, %2};" : "=l"(r) : "f"(lo), "f"(hi)); return r;
}
__device__ __forceinline__ void unpack2(ull v, float& lo, float& hi) {
    asm("mov.b64 {%0, %1}, %2;" : "=f"(lo), "=f"(hi) : "l"(v));
}
__device__ __forceinline__ ull fma2(ull a, ull b, ull c) {
    ull d; asm("fma.rn.f32x2 %0, %1, %2, %3;" : "=l"(d) : "l"(a), "l"(b), "l"(c)); return d;
}
__device__ __forceinline__ ull add2(ull a, ull b) {
    ull d; asm("add.rn.f32x2 %0, %1, %2;" : "=l"(d) : "l"(a), "l"(b)); return d;
}

// ---------------- math helpers ----------------
__device__ __forceinline__ float eluf(float z)      { return z > 0.f ? z : expm1f(z); }
__device__ __forceinline__ float sigmoidf_(float z) { return 1.f / (1.f + expf(-z)); }
__device__ __forceinline__ float softplusf_(float z){ return fmaxf(z, 0.f) + log1pf(expf(-fabsf(z))); }

// =====================================================================
// Kernel 0: build duplicated fp32 weight layouts
// =====================================================================
__global__ void convert_kernel(const float* __restrict__ gru_W,
                               const float* __restrict__ img_W,
                               const float* __restrict__ obs_out_W,
                               const float* __restrict__ ims_W,
                               const float* __restrict__ obs_W,
                               const float* __restrict__ inp_W)
{
    int i = blockIdx.x * blockDim.x + threadIdx.x;
    if (i < 400 * 200) {
        int k = i / 200, u = i % 200;
        float wr = gru_W[k * 600 + u];
        float wc = gru_W[k * 600 + 200 + u];
        float wu = gru_W[k * 600 + 400 + u];
        g_rc4[i] = make_float4(wr, wr, wc, wc);
        g_uw2[i] = make_float2(wu, wu);
    }
    if (i < 200 * 200) {
        float wi = img_W[i], wo = obs_out_W[i];
        g_io4[i] = make_float4(wi, wi, wo, wo);
    }
    if (i < 200 * 60) {
        float wa = ims_W[i], wb = obs_W[i];
        g_ef4[i] = make_float4(wa, wa, wb, wb);
    }
    if (i < 30 * 200) {
        float w = inp_W[i];
        g_in2[i] = make_float2(w, w);
    }
}

// =====================================================================
// Kernel 1: precompute (fp32, unchanged)
// =====================================================================
#define PRE_ROWS 32
#define PRE_KC   256
#define PRE_PAD  36

__global__ void __launch_bounds__(224) precompute_kernel(
    const float* __restrict__ embed,
    const float* __restrict__ action,
    const float* __restrict__ obs_out_W,
    const float* __restrict__ obs_out_b,
    const float* __restrict__ inp_W,
    const float* __restrict__ inp_b)
{
    __shared__ __align__(16) float s_aT[PRE_KC * PRE_PAD];
    __shared__ float s_act[PRE_ROWS * NA];

    const int bt0 = blockIdx.x * PRE_ROWS;
    const int tid = threadIdx.x;
    const int j   = tid;

    ull acc[16];
    {
        float b = (j < NH) ? obs_out_b[j] : 0.f;
        ull bb = pack2(b, b);
#pragma unroll
        for (int i = 0; i < 16; i++) acc[i] = bb;
    }

    const float* W2 = obs_out_W + (size_t)ND * NH;

    for (int kc = 0; kc < NE; kc += PRE_KC) {
        __syncthreads();
        for (int idx = tid; idx < PRE_ROWS * PRE_KC; idx += blockDim.x) {
            int rr = idx / PRE_KC;
            int kk = idx % PRE_KC;
            s_aT[kk * PRE_PAD + rr] = embed[(size_t)(bt0 + rr) * NE + kc + kk];
        }
        __syncthreads();

        if (j < NH) {
#pragma unroll 2
            for (int kk = 0; kk < PRE_KC; kk++) {
                float w = W2[(size_t)(kc + kk) * NH + j];
                ull wv = pack2(w, w);
                const ulonglong2* ap = (const ulonglong2*)&s_aT[kk * PRE_PAD];
#pragma unroll
                for (int q = 0; q < 8; q++) {
                    ulonglong2 a = ap[q];
                    acc[2 * q]     = fma2(a.x, wv, acc[2 * q]);
                    acc[2 * q + 1] = fma2(a.y, wv, acc[2 * q + 1]);
                }
            }
        }
    }

    if (j < NH) {
#pragma unroll
        for (int q = 0; q < 8; q++) {
            float v0, v1, v2, v3;
            unpack2(acc[2 * q],     v0, v1);
            unpack2(acc[2 * q + 1], v2, v3);
            g_pre_obs[(size_t)(bt0 + 4 * q + 0) * NH + j] = v0;
            g_pre_obs[(size_t)(bt0 + 4 * q + 1) * NH + j] = v1;
            g_pre_obs[(size_t)(bt0 + 4 * q + 2) * NH + j] = v2;
            g_pre_obs[(size_t)(bt0 + 4 * q + 3) * NH + j] = v3;
        }
    }

    __syncthreads();
    for (int idx = tid; idx < PRE_ROWS * NA; idx += blockDim.x) {
        int rr = idx / NA, kk = idx % NA;
        s_act[idx] = action[(size_t)(bt0 + rr) * NA + kk];
    }
    __syncthreads();

    if (j < NH) {
        float ib = inp_b[j];
        float wA[NA];
#pragma unroll
        for (int k = 0; k < NA; k++) wA[k] = inp_W[(NS + k) * NH + j];
        for (int rr = 0; rr < PRE_ROWS; rr++) {
            float a = ib;
#pragma unroll
            for (int k = 0; k < NA; k++) a = fmaf(s_act[rr * NA + k], wA[k], a);
            g_pre_inp[(size_t)(bt0 + rr) * NH + j] = a;
        }
    }
}

// =====================================================================
// Kernel 2: sequential scan. 128 CTAs x 4 rows, 512 threads, k-split,
// pre-duplicated fp32 weights (zero MOV tax in inner loops).
// =====================================================================
__global__ void __launch_bounds__(512) scan_kernel(
    const float* __restrict__ noise_prior,
    const float* __restrict__ noise_post,
    const float* __restrict__ gru_b,
    const float* __restrict__ img_out_b,
    const float* __restrict__ ims_b,
    const float* __restrict__ obs_b,
    float* __restrict__ out)
{
    __shared__ __align__(16) float s_xd[400 * R];   // x (0..199), deter (200..399)
    __shared__ __align__(16) float s_dn[200 * R];
    __shared__ __align__(16) float s_h [200 * R];
    __shared__ __align__(16) float s_ho[200 * R];
    __shared__ __align__(16) float s_po[200 * R];
    __shared__ __align__(16) float s_stoch[32 * R];
    __shared__ __align__(16) ull s_gp [200 * 6];
    __shared__ __align__(16) ull s_iop[200 * 4];
    __shared__ __align__(16) ull s_efp[240 * 4];    // all 4 quarters write

    const int tid  = threadIdx.x;
    const int row0 = blockIdx.x * R;

    for (int i = tid; i < 400 * R; i += 512) s_xd[i] = 0.f;
    for (int i = tid; i < 32 * R;  i += 512) s_stoch[i] = 0.f;
    __syncthreads();

    const int h400 = tid / 200;
    const int u400 = tid % 200;

    for (int t = 0; t < NT; t++) {
        // ========== Phase A: x = elu(stoch @ inp_W[:30] + pre_inp); prefetch pre_obs ==========
        if (tid < 200) {
            const int j = tid;
            size_t base = ((size_t)row0 * NT + t) * NH + j;
            ull a0 = pack2(g_pre_inp[base], g_pre_inp[base + (size_t)NT * NH]);
            ull a1 = pack2(g_pre_inp[base + 2 * (size_t)NT * NH],
                           g_pre_inp[base + 3 * (size_t)NT * NH]);
#pragma unroll
            for (int k = 0; k < NS; k++) {
                ull wv = *(const ull*)&g_in2[k * 200 + j];
                ulonglong2 av = *(const ulonglong2*)&s_stoch[k * R];
                a0 = fma2(av.x, wv, a0);
                a1 = fma2(av.y, wv, a1);
            }
            float y0, y1, y2, y3;
            unpack2(a0, y0, y1); unpack2(a1, y2, y3);
            s_xd[j * R + 0] = eluf(y0);
            s_xd[j * R + 1] = eluf(y1);
            s_xd[j * R + 2] = eluf(y2);
            s_xd[j * R + 3] = eluf(y3);
        } else if (tid >= 224 && tid < 424) {
            const int j = tid - 224;
            size_t base = ((size_t)row0 * NT + t) * NH + j;
            s_po[j * R + 0] = g_pre_obs[base];
            s_po[j * R + 1] = g_pre_obs[base + (size_t)NT * NH];
            s_po[j * R + 2] = g_pre_obs[base + 2 * (size_t)NT * NH];
            s_po[j * R + 3] = g_pre_obs[base + 3 * (size_t)NT * NH];
        }
        __syncthreads();

        // ========== Phase B: GRU, k-split x2, duplicated weights ==========
        ull pr0 = 0, pr1 = 0, pc0 = 0, pc1 = 0, pu0 = 0, pu1 = 0;
        if (tid < 400) {
            if (h400 == 0) {
                float br = gru_b[u400], bc = gru_b[200 + u400], bu = gru_b[400 + u400];
                pr0 = pack2(br, br); pr1 = pr0;
                pc0 = pack2(bc, bc); pc1 = pc0;
                pu0 = pack2(bu, bu); pu1 = pu0;
            }
            const ulonglong2* rcp = (const ulonglong2*)g_rc4 + h400 * 200 * 200 + u400;
            const ull*        uwp = (const ull*)g_uw2 + h400 * 200 * 200 + u400;
            const ulonglong2* ap  = (const ulonglong2*)s_xd + h400 * 200;
#pragma unroll 8
            for (int k = 0; k < 200; k++) {
                ulonglong2 wrc = rcp[(size_t)k * 200];   // .x=(wr,wr) .y=(wc,wc)
                ull        wu  = uwp[(size_t)k * 200];
                ulonglong2 av  = ap[k];
                pr0 = fma2(av.x, wrc.x, pr0);  pr1 = fma2(av.y, wrc.x, pr1);
                pc0 = fma2(av.x, wrc.y, pc0);  pc1 = fma2(av.y, wrc.y, pc1);
                pu0 = fma2(av.x, wu,    pu0);  pu1 = fma2(av.y, wu,    pu1);
            }
            if (h400 == 1) {
                ull* sp = &s_gp[u400 * 6];
                sp[0] = pr0; sp[1] = pr1; sp[2] = pc0;
                sp[3] = pc1; sp[4] = pu0; sp[5] = pu1;
            }
        }
        __syncthreads();

        if (tid < 200) {
            const int u = tid;
            const ull* sp = &s_gp[u * 6];
            pr0 = add2(pr0, sp[0]); pr1 = add2(pr1, sp[1]);
            pc0 = add2(pc0, sp[2]); pc1 = add2(pc1, sp[3]);
            pu0 = add2(pu0, sp[4]); pu1 = add2(pu1, sp[5]);
            float rr[R], cc[R], uu[R];
            unpack2(pr0, rr[0], rr[1]); unpack2(pr1, rr[2], rr[3]);
            unpack2(pc0, cc[0], cc[1]); unpack2(pc1, cc[2], cc[3]);
            unpack2(pu0, uu[0], uu[1]); unpack2(pu1, uu[2], uu[3]);
#pragma unroll
            for (int r = 0; r < R; r++) {
                float reset = sigmoidf_(rr[r]);
                float cand  = tanhf(reset * cc[r]);
                float upd   = sigmoidf_(uu[r] - 1.0f);
                float dold  = s_xd[(200 + u) * R + r];
                float dn    = upd * cand + (1.f - upd) * dold;
                s_dn[u * R + r] = dn;
                out[(((size_t)(row0 + r)) * NT + t) * OUTC + 180 + u] = dn;
            }
        }
        __syncthreads();

        // ========== Phase C/D: h & ho, k-split x2, duplicated weights ==========
        ull ch0 = 0, ch1 = 0, co0 = 0, co1 = 0;
        if (tid < 400) {
            if (h400 == 0) {
                float ib = img_out_b[u400];
                ch0 = pack2(ib, ib); ch1 = ch0;
            }
            const ulonglong2* wp = (const ulonglong2*)g_io4 + h400 * 100 * 200 + u400;
            const ulonglong2* ap = (const ulonglong2*)s_dn + h400 * 100;
#pragma unroll 8
            for (int k = 0; k < 100; k++) {
                ulonglong2 w  = wp[(size_t)k * 200];     // .x=(wi,wi) .y=(wo,wo)
                ulonglong2 av = ap[k];
                ch0 = fma2(av.x, w.x, ch0);  ch1 = fma2(av.y, w.x, ch1);
                co0 = fma2(av.x, w.y, co0);  co1 = fma2(av.y, w.y, co1);
            }
            if (h400 == 1) {
                ull* sp = &s_iop[u400 * 4];
                sp[0] = ch0; sp[1] = ch1; sp[2] = co0; sp[3] = co1;
            }
        }
        __syncthreads();

        if (tid < 200) {
            const int j = tid;
            const ull* sp = &s_iop[j * 4];
            ch0 = add2(ch0, sp[0]); ch1 = add2(ch1, sp[1]);
            co0 = add2(co0, sp[2]); co1 = add2(co1, sp[3]);
            ulonglong2 po = *(const ulonglong2*)&s_po[j * R];
            co0 = add2(co0, po.x);  co1 = add2(co1, po.y);
            float v0, v1, v2, v3;
            unpack2(ch0, v0, v1); unpack2(ch1, v2, v3);
            s_h[j * R + 0] = eluf(v0); s_h[j * R + 1] = eluf(v1);
            s_h[j * R + 2] = eluf(v2); s_h[j * R + 3] = eluf(v3);
            unpack2(co0, v0, v1); unpack2(co1, v2, v3);
            s_ho[j * R + 0] = eluf(v0); s_ho[j * R + 1] = eluf(v1);
            s_ho[j * R + 2] = eluf(v2); s_ho[j * R + 3] = eluf(v3);
        }
        __syncthreads();

        // ========== Phase E/F: stat layers, k-split x4; all partials to smem ==========
        if (tid < 240) {
            const int q = tid / 60, u = tid % 60;
            ull ea0 = 0, ea1 = 0, eb0 = 0, eb1 = 0;
            if (q == 0) {
                float ba = ims_b[u], bb = obs_b[u];
                ea0 = pack2(ba, ba); ea1 = ea0;
                eb0 = pack2(bb, bb); eb1 = eb0;
            }
            const ulonglong2* wp = (const ulonglong2*)g_ef4 + q * 50 * 60 + u;
            const ulonglong2* hp = (const ulonglong2*)s_h  + q * 50;
            const ulonglong2* op = (const ulonglong2*)s_ho + q * 50;
#pragma unroll 8
            for (int k = 0; k < 50; k++) {
                ulonglong2 w  = wp[(size_t)k * 60];      // .x=(wa,wa) .y=(wb,wb)
                ulonglong2 ah = hp[k];
                ulonglong2 ao = op[k];
                ea0 = fma2(ah.x, w.x, ea0);  ea1 = fma2(ah.y, w.x, ea1);
                eb0 = fma2(ao.x, w.y, eb0);  eb1 = fma2(ao.y, w.y, eb1);
            }
            ull* sp = &s_efp[tid * 4];
            sp[0] = ea0; sp[1] = ea1; sp[2] = eb0; sp[3] = eb1;
        }
        __syncthreads();

        // ========== finalize: combine E/F partials, sample, write, carry ==========
        if (tid < NS) {           // prior: uses ims (ea) cols u and 30+u
            const int u = tid;
            ull m0 = 0, m1 = 0, sdv0 = 0, sdv1 = 0;
#pragma unroll
            for (int q = 0; q < 4; q++) {
                const ull* pa = &s_efp[(q * 60 + u) * 4];
                const ull* pb = &s_efp[(q * 60 + 30 + u) * 4];
                m0   = add2(m0,   pa[0]);  m1   = add2(m1,   pa[1]);
                sdv0 = add2(sdv0, pb[0]);  sdv1 = add2(sdv1, pb[1]);
            }
            float m[R], s[R];
            unpack2(m0, m[0], m[1]);   unpack2(m1, m[2], m[3]);
            unpack2(sdv0, s[0], s[1]); unpack2(sdv1, s[2], s[3]);
#pragma unroll
            for (int r = 0; r < R; r++) {
                float sd = softplusf_(s[r]) + 0.1f;
                size_t bt = ((size_t)(row0 + r)) * NT + t;
                float nz = noise_prior[bt * NS + u];
                size_t ob = bt * OUTC;
                out[ob + 120 + u] = m[r];
                out[ob + 150 + u] = sd;
                out[ob +  90 + u] = m[r] + sd * nz;
            }
        } else if (tid >= 32 && tid < 32 + NS) {   // posterior: obs (eb)
            const int u = tid - 32;
            ull m0 = 0, m1 = 0, sdv0 = 0, sdv1 = 0;
#pragma unroll
            for (int q = 0; q < 4; q++) {
                const ull* pa = &s_efp[(q * 60 + u) * 4];
                const ull* pb = &s_efp[(q * 60 + 30 + u) * 4];
                m0   = add2(m0,   pa[2]);  m1   = add2(m1,   pa[3]);
                sdv0 = add2(sdv0, pb[2]);  sdv1 = add2(sdv1, pb[3]);
            }
            float m[R], s[R];
            unpack2(m0, m[0], m[1]);   unpack2(m1, m[2], m[3]);
            unpack2(sdv0, s[0], s[1]); unpack2(sdv1, s[2], s[3]);
#pragma unroll
            for (int r = 0; r < R; r++) {
                float sd = softplusf_(s[r]) + 0.1f;
                size_t bt = ((size_t)(row0 + r)) * NT + t;
                float nz = noise_post[bt * NS + u];
                float st = m[r] + sd * nz;
                size_t ob = bt * OUTC;
                out[ob + 30 + u] = m[r];
                out[ob + 60 + u] = sd;
                out[ob +  0 + u] = st;
                s_stoch[u * R + r] = st;
            }
        } else if (tid >= 64) {
            for (int q = tid - 64; q < ND; q += 448)
                ((float4*)(s_xd + 200 * R))[q] = ((const float4*)s_dn)[q];
        }
        __syncthreads();
    }
}

// =====================================================================
extern "C" void kernel_launch(void* const* d_in, const int* in_sizes, int n_in,
                              void* d_out, int out_size) {
    const float* embed       = (const float*)d_in[0];
    const float* action      = (const float*)d_in[1];
    const float* noise_prior = (const float*)d_in[2];
    const float* noise_post  = (const float*)d_in[3];
    const float* inp_W       = (const float*)d_in[4];
    const float* inp_b       = (const float*)d_in[5];
    const float* gru_W       = (const float*)d_in[6];
    const float* gru_b       = (const float*)d_in[7];
    const float* img_out_W   = (const float*)d_in[8];
    const float* img_out_b   = (const float*)d_in[9];
    const float* ims_W       = (const float*)d_in[10];
    const float* ims_b       = (const float*)d_in[11];
    const float* obs_out_W   = (const float*)d_in[12];
    const float* obs_out_b   = (const float*)d_in[13];
    const float* obs_W       = (const float*)d_in[14];
    const float* obs_b       = (const float*)d_in[15];
    float* out = (float*)d_out;

    convert_kernel<<<(400 * 200 + 255) / 256, 256>>>(gru_W, img_out_W, obs_out_W,
                                                     ims_W, obs_W, inp_W);
    precompute_kernel<<<(NB * NT) / PRE_ROWS, 224>>>(embed, action, obs_out_W, obs_out_b,
                                                     inp_W, inp_b);
    scan_kernel<<<NB / R, 512>>>(noise_prior, noise_post,
                                 gru_b, img_out_b, ims_b, obs_b, out);
}

// round 6
// speedup vs baseline: 1.2009x; 1.2009x over previous
#include <cuda_runtime.h>
#include <math.h>

#define NB 512
#define NT 64
#define NS 30
#define ND 200
#define NH 200
#define NA 12
#define NE 1024
#define OUTC 380
#define R 8           // batch rows per CTA
#define NCTA (NB / R) // 64

typedef unsigned long long ull;

// ---------------- device-global scratch ----------------
// GRU weights transposed by gate: g_WT[g][k][u], g in {reset,cand,update}
__device__ float g_WT[3 * 400 * 200];
__device__ float g_pre_inp[NB * NT * NH];
__device__ float g_pre_obs[NB * NT * NH];

// ---------------- packed f32x2 helpers ----------------
__device__ __forceinline__ ull pack2(float lo, float hi) {
    ull r; asm("mov.b64 %0, {%1, %2};" : "=l"(r) : "f"(lo), "f"(hi)); return r;
}
__device__ __forceinline__ void unpack2(ull v, float& lo, float& hi) {
    asm("mov.b64 {%0, %1}, %2;" : "=f"(lo), "=f"(hi) : "l"(v));
}
__device__ __forceinline__ ull fma2(ull a, ull b, ull c) {
    ull d; asm("fma.rn.f32x2 %0, %1, %2, %3;" : "=l"(d) : "l"(a), "l"(b), "l"(c)); return d;
}

// ---------------- math helpers ----------------
__device__ __forceinline__ float eluf(float z)      { return z > 0.f ? z : expm1f(z); }
__device__ __forceinline__ float sigmoidf_(float z) { return 1.f / (1.f + expf(-z)); }
__device__ __forceinline__ float softplusf_(float z){ return fmaxf(z, 0.f) + log1pf(expf(-fabsf(z))); }

// =====================================================================
// Kernel 0: transpose GRU weights by gate (fp32, exact)
// =====================================================================
__global__ void convert_kernel(const float* __restrict__ gru_W)
{
    int o = blockIdx.x * blockDim.x + threadIdx.x;   // output index
    if (o < 3 * 400 * 200) {
        int g = o / 80000;
        int rem = o % 80000;
        int k = rem / 200;
        int u = rem % 200;
        g_WT[o] = gru_W[k * 600 + g * 200 + u];
    }
}

// =====================================================================
// Kernel 1: precompute (fp32, unchanged from R3)
// =====================================================================
#define PRE_ROWS 32
#define PRE_KC   256
#define PRE_PAD  36

__global__ void __launch_bounds__(224) precompute_kernel(
    const float* __restrict__ embed,
    const float* __restrict__ action,
    const float* __restrict__ obs_out_W,
    const float* __restrict__ obs_out_b,
    const float* __restrict__ inp_W,
    const float* __restrict__ inp_b)
{
    __shared__ __align__(16) float s_aT[PRE_KC * PRE_PAD];
    __shared__ float s_act[PRE_ROWS * NA];

    const int bt0 = blockIdx.x * PRE_ROWS;
    const int tid = threadIdx.x;
    const int j   = tid;

    ull acc[16];
    {
        float b = (j < NH) ? obs_out_b[j] : 0.f;
        ull bb = pack2(b, b);
#pragma unroll
        for (int i = 0; i < 16; i++) acc[i] = bb;
    }

    const float* W2 = obs_out_W + (size_t)ND * NH;

    for (int kc = 0; kc < NE; kc += PRE_KC) {
        __syncthreads();
        for (int idx = tid; idx < PRE_ROWS * PRE_KC; idx += blockDim.x) {
            int rr = idx / PRE_KC;
            int kk = idx % PRE_KC;
            s_aT[kk * PRE_PAD + rr] = embed[(size_t)(bt0 + rr) * NE + kc + kk];
        }
        __syncthreads();

        if (j < NH) {
#pragma unroll 2
            for (int kk = 0; kk < PRE_KC; kk++) {
                float w = W2[(size_t)(kc + kk) * NH + j];
                ull wv = pack2(w, w);
                const ulonglong2* ap = (const ulonglong2*)&s_aT[kk * PRE_PAD];
#pragma unroll
                for (int q = 0; q < 8; q++) {
                    ulonglong2 a = ap[q];
                    acc[2 * q]     = fma2(a.x, wv, acc[2 * q]);
                    acc[2 * q + 1] = fma2(a.y, wv, acc[2 * q + 1]);
                }
            }
        }
    }

    if (j < NH) {
#pragma unroll
        for (int q = 0; q < 8; q++) {
            float v0, v1, v2, v3;
            unpack2(acc[2 * q],     v0, v1);
            unpack2(acc[2 * q + 1], v2, v3);
            g_pre_obs[(size_t)(bt0 + 4 * q + 0) * NH + j] = v0;
            g_pre_obs[(size_t)(bt0 + 4 * q + 1) * NH + j] = v1;
            g_pre_obs[(size_t)(bt0 + 4 * q + 2) * NH + j] = v2;
            g_pre_obs[(size_t)(bt0 + 4 * q + 3) * NH + j] = v3;
        }
    }

    __syncthreads();
    for (int idx = tid; idx < PRE_ROWS * NA; idx += blockDim.x) {
        int rr = idx / NA, kk = idx % NA;
        s_act[idx] = action[(size_t)(bt0 + rr) * NA + kk];
    }
    __syncthreads();

    if (j < NH) {
        float ib = inp_b[j];
        float wA[NA];
#pragma unroll
        for (int k = 0; k < NA; k++) wA[k] = inp_W[(NS + k) * NH + j];
        for (int rr = 0; rr < PRE_ROWS; rr++) {
            float a = ib;
#pragma unroll
            for (int k = 0; k < NA; k++) a = fmaf(s_act[rr * NA + k], wA[k], a);
            g_pre_inp[(size_t)(bt0 + rr) * NH + j] = a;
        }
    }
}

// =====================================================================
// Kernel 2: scan. 64 CTAs x 8 rows, 640 threads.
// Each output column owned by ONE thread (full-K dot) -> no partial
// buffers, scalar coalesced weight loads, fma2 over 4 row-pairs.
// =====================================================================
__global__ void __launch_bounds__(640) scan_kernel(
    const float* __restrict__ noise_prior,
    const float* __restrict__ noise_post,
    const float* __restrict__ inp_W,
    const float* __restrict__ gru_b,
    const float* __restrict__ img_out_W,
    const float* __restrict__ img_out_b,
    const float* __restrict__ ims_W,
    const float* __restrict__ ims_b,
    const float* __restrict__ obs_out_W,
    const float* __restrict__ obs_W,
    const float* __restrict__ obs_b,
    float* __restrict__ out)
{
    __shared__ __align__(16) float s_xd[400 * R];   // x (0..199), deter (200..399)
    __shared__ __align__(16) float s_dn[200 * R];   // deter_new
    __shared__ __align__(16) float s_gr[200 * R];   // GRU reset gate pre-act
    __shared__ __align__(16) float s_h [200 * R];   // GRU cand -> then h
    __shared__ __align__(16) float s_ho[200 * R];   // GRU update -> then ho
    __shared__ __align__(16) float s_stat[120 * R]; // [m*60+u][r]
    __shared__ __align__(16) float s_stoch[32 * R];

    const int tid  = threadIdx.x;
    const int row0 = blockIdx.x * R;

    for (int i = tid; i < 400 * R; i += 640) s_xd[i] = 0.f;
    for (int i = tid; i < 32 * R;  i += 640) s_stoch[i] = 0.f;
    __syncthreads();

    for (int t = 0; t < NT; t++) {
        // ========== A: x = elu(stoch @ inp_W[:30] + pre_inp)  (200 threads) ==========
        if (tid < 200) {
            const int j = tid;
            size_t base = ((size_t)row0 * NT + t) * NH + j;
            ull a[4];
#pragma unroll
            for (int q = 0; q < 4; q++)
                a[q] = pack2(g_pre_inp[base + (size_t)(2 * q) * NT * NH],
                             g_pre_inp[base + (size_t)(2 * q + 1) * NT * NH]);
#pragma unroll
            for (int k = 0; k < NS; k++) {
                float w = inp_W[k * NH + j];
                ull wv = pack2(w, w);
                const ulonglong2* av = (const ulonglong2*)&s_stoch[k * R];
                ulonglong2 v0 = av[0], v1 = av[1];
                a[0] = fma2(v0.x, wv, a[0]);
                a[1] = fma2(v0.y, wv, a[1]);
                a[2] = fma2(v1.x, wv, a[2]);
                a[3] = fma2(v1.y, wv, a[3]);
            }
#pragma unroll
            for (int q = 0; q < 4; q++) {
                float lo, hi;
                unpack2(a[q], lo, hi);
                s_xd[j * R + 2 * q]     = eluf(lo);
                s_xd[j * R + 2 * q + 1] = eluf(hi);
            }
        }
        __syncthreads();

        // ========== B: GRU dots (600 threads: gate g, column u, full K=400) ==========
        if (tid < 600) {
            const int g = tid / 200;
            const int u = tid % 200;
            float b = gru_b[g * 200 + u];
            ull a0 = pack2(b, b), a1 = a0, a2 = a0, a3 = a0;
            const float* wp = g_WT + g * 80000 + u;
            const ulonglong2* ap = (const ulonglong2*)s_xd;
#pragma unroll 8
            for (int k = 0; k < 400; k++) {
                float w = wp[k * 200];
                ull wv = pack2(w, w);
                ulonglong2 v0 = ap[2 * k], v1 = ap[2 * k + 1];
                a0 = fma2(v0.x, wv, a0);
                a1 = fma2(v0.y, wv, a1);
                a2 = fma2(v1.x, wv, a2);
                a3 = fma2(v1.y, wv, a3);
            }
            float* gbuf = (g == 0) ? s_gr : (g == 1) ? s_h : s_ho;
            float v0, v1;
            unpack2(a0, v0, v1); gbuf[u * R + 0] = v0; gbuf[u * R + 1] = v1;
            unpack2(a1, v0, v1); gbuf[u * R + 2] = v0; gbuf[u * R + 3] = v1;
            unpack2(a2, v0, v1); gbuf[u * R + 4] = v0; gbuf[u * R + 5] = v1;
            unpack2(a3, v0, v1); gbuf[u * R + 6] = v0; gbuf[u * R + 7] = v1;
        }
        __syncthreads();

        // ========== B2: gate combine -> deter_new (200 threads) ==========
        if (tid < 200) {
            const int u = tid;
#pragma unroll
            for (int r = 0; r < R; r++) {
                float reset = sigmoidf_(s_gr[u * R + r]);
                float cand  = tanhf(reset * s_h[u * R + r]);
                float upd   = sigmoidf_(s_ho[u * R + r] - 1.0f);
                float dold  = s_xd[(200 + u) * R + r];
                float dn    = upd * cand + (1.f - upd) * dold;
                s_dn[u * R + r] = dn;
                s_xd[(200 + u) * R + r] = dn;   // carry for next step
                out[(((size_t)(row0 + r)) * NT + t) * OUTC + 180 + u] = dn;
            }
        }
        __syncthreads();

        // ========== C/D: h = elu(dn@img+b), ho = elu(dn@obs_d + pre_obs) (400 thr) ==========
        if (tid < 400) {
            const int m = tid / 200;        // 0 = img, 1 = obs
            const int j = tid % 200;
            ull a0, a1, a2, a3;
            if (m == 0) {
                float b = img_out_b[j];
                a0 = pack2(b, b); a1 = a0; a2 = a0; a3 = a0;
            } else {
                size_t base = ((size_t)row0 * NT + t) * NH + j;
                a0 = pack2(g_pre_obs[base],
                           g_pre_obs[base + (size_t)NT * NH]);
                a1 = pack2(g_pre_obs[base + 2 * (size_t)NT * NH],
                           g_pre_obs[base + 3 * (size_t)NT * NH]);
                a2 = pack2(g_pre_obs[base + 4 * (size_t)NT * NH],
                           g_pre_obs[base + 5 * (size_t)NT * NH]);
                a3 = pack2(g_pre_obs[base + 6 * (size_t)NT * NH],
                           g_pre_obs[base + 7 * (size_t)NT * NH]);
            }
            const float* wp = ((m == 0) ? img_out_W : obs_out_W) + j;
            const ulonglong2* ap = (const ulonglong2*)s_dn;
#pragma unroll 8
            for (int k = 0; k < 200; k++) {
                float w = wp[k * 200];
                ull wv = pack2(w, w);
                ulonglong2 v0 = ap[2 * k], v1 = ap[2 * k + 1];
                a0 = fma2(v0.x, wv, a0);
                a1 = fma2(v0.y, wv, a1);
                a2 = fma2(v1.x, wv, a2);
                a3 = fma2(v1.y, wv, a3);
            }
            float* dst = (m == 0) ? s_h : s_ho;
            float v0, v1;
            unpack2(a0, v0, v1); dst[j * R + 0] = eluf(v0); dst[j * R + 1] = eluf(v1);
            unpack2(a1, v0, v1); dst[j * R + 2] = eluf(v0); dst[j * R + 3] = eluf(v1);
            unpack2(a2, v0, v1); dst[j * R + 4] = eluf(v0); dst[j * R + 5] = eluf(v1);
            unpack2(a3, v0, v1); dst[j * R + 6] = eluf(v0); dst[j * R + 7] = eluf(v1);
        }
        __syncthreads();

        // ========== E/F: stat layers (120 threads: m in {ims,obs}, col u of 60) ==========
        if (tid < 120) {
            const int m = tid / 60;
            const int u = tid % 60;
            float b = ((m == 0) ? ims_b : obs_b)[u];
            ull a0 = pack2(b, b), a1 = a0, a2 = a0, a3 = a0;
            const float* wp = ((m == 0) ? ims_W : obs_W) + u;
            const ulonglong2* ap = (const ulonglong2*)((m == 0) ? s_h : s_ho);
#pragma unroll 8
            for (int k = 0; k < 200; k++) {
                float w = wp[k * 60];
                ull wv = pack2(w, w);
                ulonglong2 v0 = ap[2 * k], v1 = ap[2 * k + 1];
                a0 = fma2(v0.x, wv, a0);
                a1 = fma2(v0.y, wv, a1);
                a2 = fma2(v1.x, wv, a2);
                a3 = fma2(v1.y, wv, a3);
            }
            float* dst = &s_stat[(m * 60 + u) * R];
            float v0, v1;
            unpack2(a0, v0, v1); dst[0] = v0; dst[1] = v1;
            unpack2(a1, v0, v1); dst[2] = v0; dst[3] = v1;
            unpack2(a2, v0, v1); dst[4] = v0; dst[5] = v1;
            unpack2(a3, v0, v1); dst[6] = v0; dst[7] = v1;
        }
        __syncthreads();

        // ========== finalize: sample + write + carry ==========
        if (tid < NS) {                       // prior (ims stats)
            const int u = tid;
#pragma unroll
            for (int r = 0; r < R; r++) {
                float m  = s_stat[u * R + r];
                float sd = softplusf_(s_stat[(NS + u) * R + r]) + 0.1f;
                size_t bt = ((size_t)(row0 + r)) * NT + t;
                float nz = noise_prior[bt * NS + u];
                size_t ob = bt * OUTC;
                out[ob + 120 + u] = m;
                out[ob + 150 + u] = sd;
                out[ob +  90 + u] = m + sd * nz;
            }
        } else if (tid >= 32 && tid < 32 + NS) {  // posterior (obs stats)
            const int u = tid - 32;
#pragma unroll
            for (int r = 0; r < R; r++) {
                float m  = s_stat[(60 + u) * R + r];
                float sd = softplusf_(s_stat[(60 + NS + u) * R + r]) + 0.1f;
                size_t bt = ((size_t)(row0 + r)) * NT + t;
                float nz = noise_post[bt * NS + u];
                float st = m + sd * nz;
                size_t ob = bt * OUTC;
                out[ob + 30 + u] = m;
                out[ob + 60 + u] = sd;
                out[ob +  0 + u] = st;
                s_stoch[u * R + r] = st;
            }
        }
        __syncthreads();
    }
}

// =====================================================================
extern "C" void kernel_launch(void* const* d_in, const int* in_sizes, int n_in,
                              void* d_out, int out_size) {
    const float* embed       = (const float*)d_in[0];
    const float* action      = (const float*)d_in[1];
    const float* noise_prior = (const float*)d_in[2];
    const float* noise_post  = (const float*)d_in[3];
    const float* inp_W       = (const float*)d_in[4];
    const float* inp_b       = (const float*)d_in[5];
    const float* gru_W       = (const float*)d_in[6];
    const float* gru_b       = (const float*)d_in[7];
    const float* img_out_W   = (const float*)d_in[8];
    const float* img_out_b   = (const float*)d_in[9];
    const float* ims_W       = (const float*)d_in[10];
    const float* ims_b       = (const float*)d_in[11];
    const float* obs_out_W   = (const float*)d_in[12];
    const float* obs_out_b   = (const float*)d_in[13];
    const float* obs_W       = (const float*)d_in[14];
    const float* obs_b       = (const float*)d_in[15];
    float* out = (float*)d_out;

    convert_kernel<<<(3 * 400 * 200 + 255) / 256, 256>>>(gru_W);
    precompute_kernel<<<(NB * NT) / PRE_ROWS, 224>>>(embed, action, obs_out_W, obs_out_b,
                                                     inp_W, inp_b);
    scan_kernel<<<NCTA, 640>>>(noise_prior, noise_post, inp_W, gru_b,
                               img_out_W, img_out_b, ims_W, ims_b,
                               obs_out_W, obs_W, obs_b, out);
}

// round 7
// speedup vs baseline: 1.4170x; 1.1800x over previous
#include <cuda_runtime.h>
#include <math.h>

#define NB 512
#define NT 64
#define NS 30
#define ND 200
#define NH 200
#define NA 12
#define NE 1024
#define OUTC 380
#define R 8
#define NCTA (NB / R)   // 64

typedef unsigned long long ull;

// ---------------- device-global scratch (allocation-free rule) ----------------
// Padded weight copies so register-prefetch may read up to 8-16 rows past K.
__device__ float g_WT [(400 + 8) * 600];   // gru_W padded      [k][600]
__device__ float g_IOT[(200 + 16) * 400];  // [k][ img(200) | obs_out(200) ]
__device__ float g_EFT[(200 + 16) * 120];  // [k][ ims(60) | obs(60) ]
__device__ float g_pre_inp[NB * NT * NH];
__device__ float g_pre_obs[NB * NT * NH];

// ---------------- packed f32x2 helpers ----------------
__device__ __forceinline__ ull pack2(float lo, float hi) {
    ull r; asm("mov.b64 %0, {%1, %2};" : "=l"(r) : "f"(lo), "f"(hi)); return r;
}
__device__ __forceinline__ void unpack2(ull v, float& lo, float& hi) {
    asm("mov.b64 {%0, %1}, %2;" : "=f"(lo), "=f"(hi) : "l"(v));
}
__device__ __forceinline__ ull fma2(ull a, ull b, ull c) {
    ull d; asm("fma.rn.f32x2 %0, %1, %2, %3;" : "=l"(d) : "l"(a), "l"(b), "l"(c)); return d;
}
__device__ __forceinline__ ull add2(ull a, ull b) {
    ull d; asm("add.rn.f32x2 %0, %1, %2;" : "=l"(d) : "l"(a), "l"(b)); return d;
}

// ---------------- math helpers ----------------
__device__ __forceinline__ float eluf(float z)      { return z > 0.f ? z : expm1f(z); }
__device__ __forceinline__ float sigmoidf_(float z) { return 1.f / (1.f + expf(-z)); }
__device__ __forceinline__ float softplusf_(float z){ return fmaxf(z, 0.f) + log1pf(expf(-fabsf(z))); }

// =====================================================================
// Kernel 0: build padded weight copies (fp32, exact)
// =====================================================================
__global__ void convert_kernel(const float* __restrict__ gru_W,
                               const float* __restrict__ img_W,
                               const float* __restrict__ obs_out_W,
                               const float* __restrict__ ims_W,
                               const float* __restrict__ obs_W)
{
    int i = blockIdx.x * blockDim.x + threadIdx.x;
    if (i < (400 + 8) * 600) {
        int k = i / 600;
        g_WT[i] = (k < 400) ? gru_W[i] : 0.f;
    }
    if (i < (200 + 16) * 400) {
        int k = i / 400, c = i % 400;
        float v = 0.f;
        if (k < 200) v = (c < 200) ? img_W[k * 200 + c] : obs_out_W[k * 200 + (c - 200)];
        g_IOT[i] = v;
    }
    if (i < (200 + 16) * 120) {
        int k = i / 120, c = i % 120;
        float v = 0.f;
        if (k < 200) v = (c < 60) ? ims_W[k * 60 + c] : obs_W[k * 60 + (c - 60)];
        g_EFT[i] = v;
    }
}

// =====================================================================
// Kernel 1: precompute (fp32, unchanged)
// =====================================================================
#define PRE_ROWS 32
#define PRE_KC   256
#define PRE_PAD  36

__global__ void __launch_bounds__(224) precompute_kernel(
    const float* __restrict__ embed,
    const float* __restrict__ action,
    const float* __restrict__ obs_out_W,
    const float* __restrict__ obs_out_b,
    const float* __restrict__ inp_W,
    const float* __restrict__ inp_b)
{
    __shared__ __align__(16) float s_aT[PRE_KC * PRE_PAD];
    __shared__ float s_act[PRE_ROWS * NA];

    const int bt0 = blockIdx.x * PRE_ROWS;
    const int tid = threadIdx.x;
    const int j   = tid;

    ull acc[16];
    {
        float b = (j < NH) ? obs_out_b[j] : 0.f;
        ull bb = pack2(b, b);
#pragma unroll
        for (int i = 0; i < 16; i++) acc[i] = bb;
    }

    const float* W2 = obs_out_W + (size_t)ND * NH;

    for (int kc = 0; kc < NE; kc += PRE_KC) {
        __syncthreads();
        for (int idx = tid; idx < PRE_ROWS * PRE_KC; idx += blockDim.x) {
            int rr = idx / PRE_KC;
            int kk = idx % PRE_KC;
            s_aT[kk * PRE_PAD + rr] = embed[(size_t)(bt0 + rr) * NE + kc + kk];
        }
        __syncthreads();

        if (j < NH) {
#pragma unroll 2
            for (int kk = 0; kk < PRE_KC; kk++) {
                float w = W2[(size_t)(kc + kk) * NH + j];
                ull wv = pack2(w, w);
                const ulonglong2* ap = (const ulonglong2*)&s_aT[kk * PRE_PAD];
#pragma unroll
                for (int q = 0; q < 8; q++) {
                    ulonglong2 a = ap[q];
                    acc[2 * q]     = fma2(a.x, wv, acc[2 * q]);
                    acc[2 * q + 1] = fma2(a.y, wv, acc[2 * q + 1]);
                }
            }
        }
    }

    if (j < NH) {
#pragma unroll
        for (int q = 0; q < 8; q++) {
            float v0, v1, v2, v3;
            unpack2(acc[2 * q],     v0, v1);
            unpack2(acc[2 * q + 1], v2, v3);
            g_pre_obs[(size_t)(bt0 + 4 * q + 0) * NH + j] = v0;
            g_pre_obs[(size_t)(bt0 + 4 * q + 1) * NH + j] = v1;
            g_pre_obs[(size_t)(bt0 + 4 * q + 2) * NH + j] = v2;
            g_pre_obs[(size_t)(bt0 + 4 * q + 3) * NH + j] = v3;
        }
    }

    __syncthreads();
    for (int idx = tid; idx < PRE_ROWS * NA; idx += blockDim.x) {
        int rr = idx / NA, kk = idx % NA;
        s_act[idx] = action[(size_t)(bt0 + rr) * NA + kk];
    }
    __syncthreads();

    if (j < NH) {
        float ib = inp_b[j];
        float wA[NA];
#pragma unroll
        for (int k = 0; k < NA; k++) wA[k] = inp_W[(NS + k) * NH + j];
        for (int rr = 0; rr < PRE_ROWS; rr++) {
            float a = ib;
#pragma unroll
            for (int k = 0; k < NA; k++) a = fmaf(s_act[rr * NA + k], wA[k], a);
            g_pre_inp[(size_t)(bt0 + rr) * NH + j] = a;
        }
    }
}

// =====================================================================
// Kernel 2: scan. 64 CTAs x 8 rows, 640 threads, explicit depth-8
// register prefetch of weights in every dot loop (MLP=8 guaranteed).
// =====================================================================
__global__ void __launch_bounds__(640) scan_kernel(
    const float* __restrict__ noise_prior,
    const float* __restrict__ noise_post,
    const float* __restrict__ inp_W,
    const float* __restrict__ gru_b,
    const float* __restrict__ img_out_b,
    const float* __restrict__ ims_b,
    const float* __restrict__ obs_b,
    float* __restrict__ out)
{
    __shared__ __align__(16) float s_xd[400 * R];   // x (0..199), deter (200..399)
    __shared__ __align__(16) float s_dn[200 * R];
    __shared__ __align__(16) float s_gr[200 * R];   // reset pre-act
    __shared__ __align__(16) float s_h [200 * R];   // cand pre-act -> h
    __shared__ __align__(16) float s_ho[200 * R];   // update pre-act -> ho
    __shared__ __align__(16) float s_stoch[32 * R];
    __shared__ __align__(16) ull   s_efp[240 * 4];  // E/F partials

    const int tid  = threadIdx.x;
    const int row0 = blockIdx.x * R;

    for (int i = tid; i < 400 * R; i += 640) s_xd[i] = 0.f;
    for (int i = tid; i < 32 * R;  i += 640) s_stoch[i] = 0.f;
    __syncthreads();

    for (int t = 0; t < NT; t++) {
        // ===== A: x = elu(stoch @ inp_W[:30] + pre_inp)  (200 threads) =====
        if (tid < 200) {
            const int j = tid;
            size_t base = ((size_t)row0 * NT + t) * NH + j;
            ull a0 = pack2(g_pre_inp[base],
                           g_pre_inp[base + (size_t)NT * NH]);
            ull a1 = pack2(g_pre_inp[base + 2 * (size_t)NT * NH],
                           g_pre_inp[base + 3 * (size_t)NT * NH]);
            ull a2 = pack2(g_pre_inp[base + 4 * (size_t)NT * NH],
                           g_pre_inp[base + 5 * (size_t)NT * NH]);
            ull a3 = pack2(g_pre_inp[base + 6 * (size_t)NT * NH],
                           g_pre_inp[base + 7 * (size_t)NT * NH]);
            const ulonglong2* ap = (const ulonglong2*)s_stoch;
#pragma unroll
            for (int k = 0; k < NS; k++) {
                float w = inp_W[k * NH + j];
                ull wv = pack2(w, w);
                ulonglong2 v0 = ap[2 * k], v1 = ap[2 * k + 1];
                a0 = fma2(v0.x, wv, a0);
                a1 = fma2(v0.y, wv, a1);
                a2 = fma2(v1.x, wv, a2);
                a3 = fma2(v1.y, wv, a3);
            }
            float lo, hi;
            unpack2(a0, lo, hi); s_xd[j*R+0]=eluf(lo); s_xd[j*R+1]=eluf(hi);
            unpack2(a1, lo, hi); s_xd[j*R+2]=eluf(lo); s_xd[j*R+3]=eluf(hi);
            unpack2(a2, lo, hi); s_xd[j*R+4]=eluf(lo); s_xd[j*R+5]=eluf(hi);
            unpack2(a3, lo, hi); s_xd[j*R+6]=eluf(lo); s_xd[j*R+7]=eluf(hi);
        }
        __syncthreads();

        // ===== B: GRU dots (600 threads; col = tid; K=400; prefetch-8) =====
        if (tid < 600) {
            float b = gru_b[tid];
            ull a0 = pack2(b, b), a1 = a0, a2 = a0, a3 = a0;
            const float* wp = g_WT + tid;
            const ulonglong2* ap = (const ulonglong2*)s_xd;
            float w[8];
#pragma unroll
            for (int i = 0; i < 8; i++) w[i] = wp[i * 600];
            for (int kb = 0; kb < 400; kb += 8) {
                float wn[8];
#pragma unroll
                for (int i = 0; i < 8; i++) wn[i] = wp[(kb + 8 + i) * 600];
#pragma unroll
                for (int i = 0; i < 8; i++) {
                    ull wv = pack2(w[i], w[i]);
                    ulonglong2 v0 = ap[(kb + i) * 2], v1 = ap[(kb + i) * 2 + 1];
                    a0 = fma2(v0.x, wv, a0);
                    a1 = fma2(v0.y, wv, a1);
                    a2 = fma2(v1.x, wv, a2);
                    a3 = fma2(v1.y, wv, a3);
                }
#pragma unroll
                for (int i = 0; i < 8; i++) w[i] = wn[i];
            }
            const int g = tid / 200, u = tid % 200;
            float* gbuf = (g == 0) ? s_gr : (g == 1) ? s_h : s_ho;
            float lo, hi;
            unpack2(a0, lo, hi); gbuf[u*R+0]=lo; gbuf[u*R+1]=hi;
            unpack2(a1, lo, hi); gbuf[u*R+2]=lo; gbuf[u*R+3]=hi;
            unpack2(a2, lo, hi); gbuf[u*R+4]=lo; gbuf[u*R+5]=hi;
            unpack2(a3, lo, hi); gbuf[u*R+6]=lo; gbuf[u*R+7]=hi;
        }
        __syncthreads();

        // ===== B2: gate combine -> deter_new (200 threads) =====
        if (tid < 200) {
            const int u = tid;
#pragma unroll
            for (int r = 0; r < R; r++) {
                float reset = sigmoidf_(s_gr[u * R + r]);
                float cand  = tanhf(reset * s_h[u * R + r]);
                float upd   = sigmoidf_(s_ho[u * R + r] - 1.0f);
                float dold  = s_xd[(200 + u) * R + r];
                float dn    = upd * cand + (1.f - upd) * dold;
                s_dn[u * R + r] = dn;
                s_xd[(200 + u) * R + r] = dn;
                out[(((size_t)(row0 + r)) * NT + t) * OUTC + 180 + u] = dn;
            }
        }
        __syncthreads();

        // ===== C/D: h / ho (400 threads; col = tid of [img|obs]; K=200) =====
        if (tid < 400) {
            const int m = tid / 200;
            const int j = tid % 200;
            ull a0, a1, a2, a3;
            if (m == 0) {
                float b = img_out_b[j];
                a0 = pack2(b, b); a1 = a0; a2 = a0; a3 = a0;
            } else {
                size_t base = ((size_t)row0 * NT + t) * NH + j;
                a0 = pack2(g_pre_obs[base],
                           g_pre_obs[base + (size_t)NT * NH]);
                a1 = pack2(g_pre_obs[base + 2 * (size_t)NT * NH],
                           g_pre_obs[base + 3 * (size_t)NT * NH]);
                a2 = pack2(g_pre_obs[base + 4 * (size_t)NT * NH],
                           g_pre_obs[base + 5 * (size_t)NT * NH]);
                a3 = pack2(g_pre_obs[base + 6 * (size_t)NT * NH],
                           g_pre_obs[base + 7 * (size_t)NT * NH]);
            }
            const float* wp = g_IOT + tid;
            const ulonglong2* ap = (const ulonglong2*)s_dn;
            float w[8];
#pragma unroll
            for (int i = 0; i < 8; i++) w[i] = wp[i * 400];
            for (int kb = 0; kb < 200; kb += 8) {
                float wn[8];
#pragma unroll
                for (int i = 0; i < 8; i++) wn[i] = wp[(kb + 8 + i) * 400];
#pragma unroll
                for (int i = 0; i < 8; i++) {
                    ull wv = pack2(w[i], w[i]);
                    ulonglong2 v0 = ap[(kb + i) * 2], v1 = ap[(kb + i) * 2 + 1];
                    a0 = fma2(v0.x, wv, a0);
                    a1 = fma2(v0.y, wv, a1);
                    a2 = fma2(v1.x, wv, a2);
                    a3 = fma2(v1.y, wv, a3);
                }
#pragma unroll
                for (int i = 0; i < 8; i++) w[i] = wn[i];
            }
            float* dst = (m == 0) ? s_h : s_ho;
            float lo, hi;
            unpack2(a0, lo, hi); dst[j*R+0]=eluf(lo); dst[j*R+1]=eluf(hi);
            unpack2(a1, lo, hi); dst[j*R+2]=eluf(lo); dst[j*R+3]=eluf(hi);
            unpack2(a2, lo, hi); dst[j*R+4]=eluf(lo); dst[j*R+5]=eluf(hi);
            unpack2(a3, lo, hi); dst[j*R+6]=eluf(lo); dst[j*R+7]=eluf(hi);
        }
        __syncthreads();

        // ===== E/F: stat layers, k-split x2 (240 threads; K=100 each) =====
        if (tid < 240) {
            const int q = tid / 120;       // k-slice
            const int c = tid % 120;       // stat column (0..59 ims, 60..119 obs)
            const int m = c / 60;
            ull a0 = 0, a1 = 0, a2 = 0, a3 = 0;
            if (q == 0) {
                float b = (m == 0) ? ims_b[c] : obs_b[c - 60];
                a0 = pack2(b, b); a1 = a0; a2 = a0; a3 = a0;
            }
            const float* wp = g_EFT + (q * 100) * 120 + c;
            const ulonglong2* ap = (const ulonglong2*)((m == 0) ? s_h : s_ho)
                                   + (q * 100) * 2;
            float w[8];
#pragma unroll
            for (int i = 0; i < 8; i++) w[i] = wp[i * 120];
            for (int kb = 0; kb < 96; kb += 8) {
                float wn[8];
#pragma unroll
                for (int i = 0; i < 8; i++) wn[i] = wp[(kb + 8 + i) * 120];
#pragma unroll
                for (int i = 0; i < 8; i++) {
                    ull wv = pack2(w[i], w[i]);
                    ulonglong2 v0 = ap[(kb + i) * 2], v1 = ap[(kb + i) * 2 + 1];
                    a0 = fma2(v0.x, wv, a0);
                    a1 = fma2(v0.y, wv, a1);
                    a2 = fma2(v1.x, wv, a2);
                    a3 = fma2(v1.y, wv, a3);
                }
#pragma unroll
                for (int i = 0; i < 8; i++) w[i] = wn[i];
            }
            // tail k = 96..99
#pragma unroll
            for (int i = 0; i < 4; i++) {
                float wt = wp[(96 + i) * 120];
                ull wv = pack2(wt, wt);
                ulonglong2 v0 = ap[(96 + i) * 2], v1 = ap[(96 + i) * 2 + 1];
                a0 = fma2(v0.x, wv, a0);
                a1 = fma2(v0.y, wv, a1);
                a2 = fma2(v1.x, wv, a2);
                a3 = fma2(v1.y, wv, a3);
            }
            ull* sp = &s_efp[tid * 4];
            sp[0] = a0; sp[1] = a1; sp[2] = a2; sp[3] = a3;
        }
        __syncthreads();

        // ===== finalize: combine partials, sample, write, carry =====
        if (tid < NS) {                       // prior (ims stats)
            const int u = tid;
            ull m0=0,m1=0,m2=0,m3=0, s0=0,s1=0,s2=0,s3=0;
#pragma unroll
            for (int q = 0; q < 2; q++) {
                const ull* pm = &s_efp[(q * 120 + u) * 4];
                const ull* ps = &s_efp[(q * 120 + 30 + u) * 4];
                m0=add2(m0,pm[0]); m1=add2(m1,pm[1]); m2=add2(m2,pm[2]); m3=add2(m3,pm[3]);
                s0=add2(s0,ps[0]); s1=add2(s1,ps[1]); s2=add2(s2,ps[2]); s3=add2(s3,ps[3]);
            }
            float mm[R], ss[R];
            unpack2(m0,mm[0],mm[1]); unpack2(m1,mm[2],mm[3]);
            unpack2(m2,mm[4],mm[5]); unpack2(m3,mm[6],mm[7]);
            unpack2(s0,ss[0],ss[1]); unpack2(s1,ss[2],ss[3]);
            unpack2(s2,ss[4],ss[5]); unpack2(s3,ss[6],ss[7]);
#pragma unroll
            for (int r = 0; r < R; r++) {
                float sd = softplusf_(ss[r]) + 0.1f;
                size_t bt = ((size_t)(row0 + r)) * NT + t;
                float nz = noise_prior[bt * NS + u];
                size_t ob = bt * OUTC;
                out[ob + 120 + u] = mm[r];
                out[ob + 150 + u] = sd;
                out[ob +  90 + u] = mm[r] + sd * nz;
            }
        } else if (tid >= 32 && tid < 32 + NS) {  // posterior (obs stats)
            const int u = tid - 32;
            ull m0=0,m1=0,m2=0,m3=0, s0=0,s1=0,s2=0,s3=0;
#pragma unroll
            for (int q = 0; q < 2; q++) {
                const ull* pm = &s_efp[(q * 120 + 60 + u) * 4];
                const ull* ps = &s_efp[(q * 120 + 90 + u) * 4];
                m0=add2(m0,pm[0]); m1=add2(m1,pm[1]); m2=add2(m2,pm[2]); m3=add2(m3,pm[3]);
                s0=add2(s0,ps[0]); s1=add2(s1,ps[1]); s2=add2(s2,ps[2]); s3=add2(s3,ps[3]);
            }
            float mm[R], ss[R];
            unpack2(m0,mm[0],mm[1]); unpack2(m1,mm[2],mm[3]);
            unpack2(m2,mm[4],mm[5]); unpack2(m3,mm[6],mm[7]);
            unpack2(s0,ss[0],ss[1]); unpack2(s1,ss[2],ss[3]);
            unpack2(s2,ss[4],ss[5]); unpack2(s3,ss[6],ss[7]);
#pragma unroll
            for (int r = 0; r < R; r++) {
                float sd = softplusf_(ss[r]) + 0.1f;
                size_t bt = ((size_t)(row0 + r)) * NT + t;
                float nz = noise_post[bt * NS + u];
                float st = mm[r] + sd * nz;
                size_t ob = bt * OUTC;
                out[ob + 30 + u] = mm[r];
                out[ob + 60 + u] = sd;
                out[ob +  0 + u] = st;
                s_stoch[u * R + r] = st;
            }
        }
        __syncthreads();
    }
}

// =====================================================================
extern "C" void kernel_launch(void* const* d_in, const int* in_sizes, int n_in,
                              void* d_out, int out_size) {
    const float* embed       = (const float*)d_in[0];
    const float* action      = (const float*)d_in[1];
    const float* noise_prior = (const float*)d_in[2];
    const float* noise_post  = (const float*)d_in[3];
    const float* inp_W       = (const float*)d_in[4];
    const float* inp_b       = (const float*)d_in[5];
    const float* gru_W       = (const float*)d_in[6];
    const float* gru_b       = (const float*)d_in[7];
    const float* img_out_W   = (const float*)d_in[8];
    const float* img_out_b   = (const float*)d_in[9];
    const float* ims_W       = (const float*)d_in[10];
    const float* ims_b       = (const float*)d_in[11];
    const float* obs_out_W   = (const float*)d_in[12];
    const float* obs_out_b   = (const float*)d_in[13];
    const float* obs_W       = (const float*)d_in[14];
    const float* obs_b       = (const float*)d_in[15];
    float* out = (float*)d_out;

    convert_kernel<<<((400 + 8) * 600 + 255) / 256, 256>>>(gru_W, img_out_W, obs_out_W,
                                                           ims_W, obs_W);
    precompute_kernel<<<(NB * NT) / PRE_ROWS, 224>>>(embed, action, obs_out_W, obs_out_b,
                                                     inp_W, inp_b);
    scan_kernel<<<NCTA, 640>>>(noise_prior, noise_post, inp_W, gru_b,
                               img_out_b, ims_b, obs_b, out);
}

// round 8
// speedup vs baseline: 1.8545x; 1.3088x over previous
#include <cuda_runtime.h>
#include <math.h>

#define NB 512
#define NT 64
#define NS 30
#define ND 200
#define NH 200
#define NA 12
#define NE 1024
#define OUTC 380
#define R 4
#define NCTA (NB / R)   // 128

typedef unsigned long long ull;

// ---------------- device-global scratch (allocation-free rule) ----------------
// k-paired float2 weights: Wp[k2][c] = (W[2*k2][c], W[2*k2+1][c]); padded in k2
// so prefetch may overrun.
__device__ __align__(16) float2 g_Wp [208 * 600];  // GRU
__device__ __align__(16) float2 g_IOp[108 * 400];  // [img(200)|obs_out(200)]
__device__ __align__(16) float2 g_EFp[108 * 120];  // [ims(60)|obs(60)]
__device__ float g_pre_inp[NB * NT * NH];
__device__ float g_pre_obs[NB * NT * NH];

// ---------------- packed f32x2 helpers ----------------
__device__ __forceinline__ ull pack2(float lo, float hi) {
    ull r; asm("mov.b64 %0, {%1, %2};" : "=l"(r) : "f"(lo), "f"(hi)); return r;
}
__device__ __forceinline__ void unpack2(ull v, float& lo, float& hi) {
    asm("mov.b64 {%0, %1}, %2;" : "=f"(lo), "=f"(hi) : "l"(v));
}
__device__ __forceinline__ ull fma2(ull a, ull b, ull c) {
    ull d; asm("fma.rn.f32x2 %0, %1, %2, %3;" : "=l"(d) : "l"(a), "l"(b), "l"(c)); return d;
}
__device__ __forceinline__ ull add2(ull a, ull b) {
    ull d; asm("add.rn.f32x2 %0, %1, %2;" : "=l"(d) : "l"(a), "l"(b)); return d;
}

// ---------------- math helpers ----------------
__device__ __forceinline__ float eluf(float z)      { return z > 0.f ? z : expm1f(z); }
__device__ __forceinline__ float sigmoidf_(float z) { return 1.f / (1.f + expf(-z)); }
__device__ __forceinline__ float softplusf_(float z){ return fmaxf(z, 0.f) + log1pf(expf(-fabsf(z))); }

// =====================================================================
// Kernel 0: build k-paired weight layouts (fp32, exact)
// =====================================================================
__global__ void convert_kernel(const float* __restrict__ gru_W,
                               const float* __restrict__ img_W,
                               const float* __restrict__ obs_out_W,
                               const float* __restrict__ ims_W,
                               const float* __restrict__ obs_W)
{
    int i = blockIdx.x * blockDim.x + threadIdx.x;
    if (i < 208 * 600) {
        int k2 = i / 600, c = i % 600;
        float lo = (2 * k2     < 400) ? gru_W[(2 * k2)     * 600 + c] : 0.f;
        float hi = (2 * k2 + 1 < 400) ? gru_W[(2 * k2 + 1) * 600 + c] : 0.f;
        g_Wp[i] = make_float2(lo, hi);
    }
    if (i < 108 * 400) {
        int k2 = i / 400, c = i % 400;
        float lo = 0.f, hi = 0.f;
        int k0 = 2 * k2, k1 = 2 * k2 + 1;
        if (k0 < 200) lo = (c < 200) ? img_W[k0 * 200 + c] : obs_out_W[k0 * 200 + c - 200];
        if (k1 < 200) hi = (c < 200) ? img_W[k1 * 200 + c] : obs_out_W[k1 * 200 + c - 200];
        g_IOp[i] = make_float2(lo, hi);
    }
    if (i < 108 * 120) {
        int k2 = i / 120, c = i % 120;
        float lo = 0.f, hi = 0.f;
        int k0 = 2 * k2, k1 = 2 * k2 + 1;
        if (k0 < 200) lo = (c < 60) ? ims_W[k0 * 60 + c] : obs_W[k0 * 60 + c - 60];
        if (k1 < 200) hi = (c < 60) ? ims_W[k1 * 60 + c] : obs_W[k1 * 60 + c - 60];
        g_EFp[i] = make_float2(lo, hi);
    }
}

// =====================================================================
// Kernel 1: precompute (fp32, unchanged)
// =====================================================================
#define PRE_ROWS 32
#define PRE_KC   256
#define PRE_PAD  36

__global__ void __launch_bounds__(224) precompute_kernel(
    const float* __restrict__ embed,
    const float* __restrict__ action,
    const float* __restrict__ obs_out_W,
    const float* __restrict__ obs_out_b,
    const float* __restrict__ inp_W,
    const float* __restrict__ inp_b)
{
    __shared__ __align__(16) float s_aT[PRE_KC * PRE_PAD];
    __shared__ float s_act[PRE_ROWS * NA];

    const int bt0 = blockIdx.x * PRE_ROWS;
    const int tid = threadIdx.x;
    const int j   = tid;

    ull acc[16];
    {
        float b = (j < NH) ? obs_out_b[j] : 0.f;
        ull bb = pack2(b, b);
#pragma unroll
        for (int i = 0; i < 16; i++) acc[i] = bb;
    }

    const float* W2 = obs_out_W + (size_t)ND * NH;

    for (int kc = 0; kc < NE; kc += PRE_KC) {
        __syncthreads();
        for (int idx = tid; idx < PRE_ROWS * PRE_KC; idx += blockDim.x) {
            int rr = idx / PRE_KC;
            int kk = idx % PRE_KC;
            s_aT[kk * PRE_PAD + rr] = embed[(size_t)(bt0 + rr) * NE + kc + kk];
        }
        __syncthreads();

        if (j < NH) {
#pragma unroll 2
            for (int kk = 0; kk < PRE_KC; kk++) {
                float w = W2[(size_t)(kc + kk) * NH + j];
                ull wv = pack2(w, w);
                const ulonglong2* ap = (const ulonglong2*)&s_aT[kk * PRE_PAD];
#pragma unroll
                for (int q = 0; q < 8; q++) {
                    ulonglong2 a = ap[q];
                    acc[2 * q]     = fma2(a.x, wv, acc[2 * q]);
                    acc[2 * q + 1] = fma2(a.y, wv, acc[2 * q + 1]);
                }
            }
        }
    }

    if (j < NH) {
#pragma unroll
        for (int q = 0; q < 8; q++) {
            float v0, v1, v2, v3;
            unpack2(acc[2 * q],     v0, v1);
            unpack2(acc[2 * q + 1], v2, v3);
            g_pre_obs[(size_t)(bt0 + 4 * q + 0) * NH + j] = v0;
            g_pre_obs[(size_t)(bt0 + 4 * q + 1) * NH + j] = v1;
            g_pre_obs[(size_t)(bt0 + 4 * q + 2) * NH + j] = v2;
            g_pre_obs[(size_t)(bt0 + 4 * q + 3) * NH + j] = v3;
        }
    }

    __syncthreads();
    for (int idx = tid; idx < PRE_ROWS * NA; idx += blockDim.x) {
        int rr = idx / NA, kk = idx % NA;
        s_act[idx] = action[(size_t)(bt0 + rr) * NA + kk];
    }
    __syncthreads();

    if (j < NH) {
        float ib = inp_b[j];
        float wA[NA];
#pragma unroll
        for (int k = 0; k < NA; k++) wA[k] = inp_W[(NS + k) * NH + j];
        for (int rr = 0; rr < PRE_ROWS; rr++) {
            float a = ib;
#pragma unroll
            for (int k = 0; k < NA; k++) a = fmaf(s_act[rr * NA + k], wA[k], a);
            g_pre_inp[(size_t)(bt0 + rr) * NH + j] = a;
        }
    }
}

// =====================================================================
// Kernel 2: scan. 128 CTAs x 4 rows, 640 threads, k-paired float2
// weights with depth-4-pair register prefetch, dual accumulators.
// =====================================================================
__global__ void __launch_bounds__(640) scan_kernel(
    const float* __restrict__ noise_prior,
    const float* __restrict__ noise_post,
    const float* __restrict__ inp_W,
    const float* __restrict__ gru_b,
    const float* __restrict__ img_out_b,
    const float* __restrict__ ims_b,
    const float* __restrict__ obs_b,
    float* __restrict__ out)
{
    __shared__ __align__(16) float s_xd[400 * R];   // x (0..199), deter (200..399)
    __shared__ __align__(16) float s_dn[200 * R];
    __shared__ __align__(16) float s_gr[200 * R];
    __shared__ __align__(16) float s_h [200 * R];
    __shared__ __align__(16) float s_ho[200 * R];
    __shared__ __align__(16) float s_stat[120 * R];
    __shared__ __align__(16) float s_stoch[32 * R];

    const int tid  = threadIdx.x;
    const int row0 = blockIdx.x * R;

    for (int i = tid; i < 400 * R; i += 640) s_xd[i] = 0.f;
    for (int i = tid; i < 32 * R;  i += 640) s_stoch[i] = 0.f;
    __syncthreads();

    for (int t = 0; t < NT; t++) {
        // ===== A: x = elu(stoch @ inp_W[:30] + pre_inp)  (200 threads) =====
        if (tid < 200) {
            const int j = tid;
            size_t base = ((size_t)row0 * NT + t) * NH + j;
            ull a0 = pack2(g_pre_inp[base],
                           g_pre_inp[base + (size_t)NT * NH]);
            ull a1 = pack2(g_pre_inp[base + 2 * (size_t)NT * NH],
                           g_pre_inp[base + 3 * (size_t)NT * NH]);
            const ulonglong2* ap = (const ulonglong2*)s_stoch;
#pragma unroll
            for (int k = 0; k < NS; k++) {
                float w = inp_W[k * NH + j];
                ull wv = pack2(w, w);
                ulonglong2 v = ap[k];
                a0 = fma2(v.x, wv, a0);
                a1 = fma2(v.y, wv, a1);
            }
            float lo, hi;
            unpack2(a0, lo, hi); s_xd[j*R+0]=eluf(lo); s_xd[j*R+1]=eluf(hi);
            unpack2(a1, lo, hi); s_xd[j*R+2]=eluf(lo); s_xd[j*R+3]=eluf(hi);
        }
        __syncthreads();

        // ===== B: GRU dots (600 threads; col=tid; K=400 as 200 pairs) =====
        if (tid < 600) {
            float b = gru_b[tid];
            ull a0 = pack2(b, b), a1 = a0;      // even-k acc
            ull c0 = 0, c1 = 0;                 // odd-k acc
            const float2* wp = g_Wp + tid;
            const ulonglong2* ap = (const ulonglong2*)s_xd;  // ap[k] = 4 rows
            float2 w[4];
#pragma unroll
            for (int i = 0; i < 4; i++) w[i] = wp[i * 600];
            for (int kb = 0; kb < 200; kb += 4) {
                float2 wn[4];
#pragma unroll
                for (int i = 0; i < 4; i++) wn[i] = wp[(kb + 4 + i) * 600];
#pragma unroll
                for (int i = 0; i < 4; i++) {
                    int k2 = kb + i;
                    ull wv0 = pack2(w[i].x, w[i].x);
                    ull wv1 = pack2(w[i].y, w[i].y);
                    ulonglong2 vA = ap[2 * k2];
                    ulonglong2 vB = ap[2 * k2 + 1];
                    a0 = fma2(vA.x, wv0, a0);  a1 = fma2(vA.y, wv0, a1);
                    c0 = fma2(vB.x, wv1, c0);  c1 = fma2(vB.y, wv1, c1);
                }
#pragma unroll
                for (int i = 0; i < 4; i++) w[i] = wn[i];
            }
            a0 = add2(a0, c0); a1 = add2(a1, c1);
            const int g = tid / 200, u = tid % 200;
            float* gbuf = (g == 0) ? s_gr : (g == 1) ? s_h : s_ho;
            float lo, hi;
            unpack2(a0, lo, hi); gbuf[u*R+0]=lo; gbuf[u*R+1]=hi;
            unpack2(a1, lo, hi); gbuf[u*R+2]=lo; gbuf[u*R+3]=hi;
        }
        __syncthreads();

        // ===== B2: gate combine -> deter_new (200 threads) =====
        if (tid < 200) {
            const int u = tid;
#pragma unroll
            for (int r = 0; r < R; r++) {
                float reset = sigmoidf_(s_gr[u * R + r]);
                float cand  = tanhf(reset * s_h[u * R + r]);
                float upd   = sigmoidf_(s_ho[u * R + r] - 1.0f);
                float dold  = s_xd[(200 + u) * R + r];
                float dn    = upd * cand + (1.f - upd) * dold;
                s_dn[u * R + r] = dn;
                s_xd[(200 + u) * R + r] = dn;
                out[(((size_t)(row0 + r)) * NT + t) * OUTC + 180 + u] = dn;
            }
        }
        __syncthreads();

        // ===== C/D: h / ho (400 threads; K=200 as 100 pairs) =====
        if (tid < 400) {
            const int m = tid / 200;
            const int j = tid % 200;
            ull a0, a1;
            if (m == 0) {
                float b = img_out_b[j];
                a0 = pack2(b, b); a1 = a0;
            } else {
                size_t base = ((size_t)row0 * NT + t) * NH + j;
                a0 = pack2(g_pre_obs[base],
                           g_pre_obs[base + (size_t)NT * NH]);
                a1 = pack2(g_pre_obs[base + 2 * (size_t)NT * NH],
                           g_pre_obs[base + 3 * (size_t)NT * NH]);
            }
            ull c0 = 0, c1 = 0;
            const float2* wp = g_IOp + tid;
            const ulonglong2* ap = (const ulonglong2*)s_dn;
            float2 w[4];
#pragma unroll
            for (int i = 0; i < 4; i++) w[i] = wp[i * 400];
            for (int kb = 0; kb < 100; kb += 4) {
                float2 wn[4];
#pragma unroll
                for (int i = 0; i < 4; i++) wn[i] = wp[(kb + 4 + i) * 400];
#pragma unroll
                for (int i = 0; i < 4; i++) {
                    int k2 = kb + i;
                    ull wv0 = pack2(w[i].x, w[i].x);
                    ull wv1 = pack2(w[i].y, w[i].y);
                    ulonglong2 vA = ap[2 * k2];
                    ulonglong2 vB = ap[2 * k2 + 1];
                    a0 = fma2(vA.x, wv0, a0);  a1 = fma2(vA.y, wv0, a1);
                    c0 = fma2(vB.x, wv1, c0);  c1 = fma2(vB.y, wv1, c1);
                }
#pragma unroll
                for (int i = 0; i < 4; i++) w[i] = wn[i];
            }
            a0 = add2(a0, c0); a1 = add2(a1, c1);
            float* dst = (m == 0) ? s_h : s_ho;
            float lo, hi;
            unpack2(a0, lo, hi); dst[j*R+0]=eluf(lo); dst[j*R+1]=eluf(hi);
            unpack2(a1, lo, hi); dst[j*R+2]=eluf(lo); dst[j*R+3]=eluf(hi);
        }
        __syncthreads();

        // ===== E/F: stat layers (120 threads; K=200 as 100 pairs) =====
        if (tid < 120) {
            const int m = tid / 60;
            const int u = tid % 60;
            float b = ((m == 0) ? ims_b : obs_b)[u];
            ull a0 = pack2(b, b), a1 = a0;
            ull c0 = 0, c1 = 0;
            const float2* wp = g_EFp + tid;
            const ulonglong2* ap = (const ulonglong2*)((m == 0) ? s_h : s_ho);
            float2 w[4];
#pragma unroll
            for (int i = 0; i < 4; i++) w[i] = wp[i * 120];
            for (int kb = 0; kb < 100; kb += 4) {
                float2 wn[4];
#pragma unroll
                for (int i = 0; i < 4; i++) wn[i] = wp[(kb + 4 + i) * 120];
#pragma unroll
                for (int i = 0; i < 4; i++) {
                    int k2 = kb + i;
                    ull wv0 = pack2(w[i].x, w[i].x);
                    ull wv1 = pack2(w[i].y, w[i].y);
                    ulonglong2 vA = ap[2 * k2];
                    ulonglong2 vB = ap[2 * k2 + 1];
                    a0 = fma2(vA.x, wv0, a0);  a1 = fma2(vA.y, wv0, a1);
                    c0 = fma2(vB.x, wv1, c0);  c1 = fma2(vB.y, wv1, c1);
                }
#pragma unroll
                for (int i = 0; i < 4; i++) w[i] = wn[i];
            }
            a0 = add2(a0, c0); a1 = add2(a1, c1);
            float* dst = &s_stat[tid * R];
            float lo, hi;
            unpack2(a0, lo, hi); dst[0] = lo; dst[1] = hi;
            unpack2(a1, lo, hi); dst[2] = lo; dst[3] = hi;
        }
        __syncthreads();

        // ===== finalize: sample + write + carry =====
        if (tid < NS) {
            const int u = tid;
#pragma unroll
            for (int r = 0; r < R; r++) {
                float m  = s_stat[u * R + r];
                float sd = softplusf_(s_stat[(NS + u) * R + r]) + 0.1f;
                size_t bt = ((size_t)(row0 + r)) * NT + t;
                float nz = noise_prior[bt * NS + u];
                size_t ob = bt * OUTC;
                out[ob + 120 + u] = m;
                out[ob + 150 + u] = sd;
                out[ob +  90 + u] = m + sd * nz;
            }
        } else if (tid >= 32 && tid < 32 + NS) {
            const int u = tid - 32;
#pragma unroll
            for (int r = 0; r < R; r++) {
                float m  = s_stat[(60 + u) * R + r];
                float sd = softplusf_(s_stat[(60 + NS + u) * R + r]) + 0.1f;
                size_t bt = ((size_t)(row0 + r)) * NT + t;
                float nz = noise_post[bt * NS + u];
                float st = m + sd * nz;
                size_t ob = bt * OUTC;
                out[ob + 30 + u] = m;
                out[ob + 60 + u] = sd;
                out[ob +  0 + u] = st;
                s_stoch[u * R + r] = st;
            }
        }
        __syncthreads();
    }
}

// =====================================================================
extern "C" void kernel_launch(void* const* d_in, const int* in_sizes, int n_in,
                              void* d_out, int out_size) {
    const float* embed       = (const float*)d_in[0];
    const float* action      = (const float*)d_in[1];
    const float* noise_prior = (const float*)d_in[2];
    const float* noise_post  = (const float*)d_in[3];
    const float* inp_W       = (const float*)d_in[4];
    const float* inp_b       = (const float*)d_in[5];
    const float* gru_W       = (const float*)d_in[6];
    const float* gru_b       = (const float*)d_in[7];
    const float* img_out_W   = (const float*)d_in[8];
    const float* img_out_b   = (const float*)d_in[9];
    const float* ims_W       = (const float*)d_in[10];
    const float* ims_b       = (const float*)d_in[11];
    const float* obs_out_W   = (const float*)d_in[12];
    const float* obs_out_b   = (const float*)d_in[13];
    const float* obs_W       = (const float*)d_in[14];
    const float* obs_b       = (const float*)d_in[15];
    float* out = (float*)d_out;

    convert_kernel<<<(208 * 600 + 255) / 256, 256>>>(gru_W, img_out_W, obs_out_W,
                                                     ims_W, obs_W);
    precompute_kernel<<<(NB * NT) / PRE_ROWS, 224>>>(embed, action, obs_out_W, obs_out_b,
                                                     inp_W, inp_b);
    scan_kernel<<<NCTA, 640>>>(noise_prior, noise_post, inp_W, gru_b,
                               img_out_b, ims_b, obs_b, out);
}

// round 9
// speedup vs baseline: 2.1267x; 1.1468x over previous
#include <cuda_runtime.h>
#include <math.h>

#define NB 512
#define NT 64
#define NS 30
#define ND 200
#define NH 200
#define NA 12
#define NE 1024
#define OUTC 380
#define R 4
#define NCTA (NB / R)   // 128

typedef unsigned long long ull;

// ---------------- device-global scratch (allocation-free rule) ----------------
// k-quad float4 weights: Wq[k4][c] = (W[4k4][c], W[4k4+1][c], W[4k4+2][c], W[4k4+3][c])
// padded in k4 so prefetch may overrun.
__device__ __align__(16) float4 g_Wq [102 * 600];  // GRU   (100 quads + pad)
__device__ __align__(16) float4 g_IOq[ 52 * 400];  // [img(200)|obs_out(200)] (50 quads + pad)
__device__ __align__(16) float2 g_EFp[104 * 120];  // [ims(60)|obs(60)] k-pairs + pad
__device__ float g_pre_inp[NB * NT * NH];
__device__ float g_pre_obs[NB * NT * NH];

// ---------------- packed f32x2 helpers ----------------
__device__ __forceinline__ ull pack2(float lo, float hi) {
    ull r; asm("mov.b64 %0, {%1, %2};" : "=l"(r) : "f"(lo), "f"(hi)); return r;
}
__device__ __forceinline__ void unpack2(ull v, float& lo, float& hi) {
    asm("mov.b64 {%0, %1}, %2;" : "=f"(lo), "=f"(hi) : "l"(v));
}
__device__ __forceinline__ ull fma2(ull a, ull b, ull c) {
    ull d; asm("fma.rn.f32x2 %0, %1, %2, %3;" : "=l"(d) : "l"(a), "l"(b), "l"(c)); return d;
}
__device__ __forceinline__ ull add2(ull a, ull b) {
    ull d; asm("add.rn.f32x2 %0, %1, %2;" : "=l"(d) : "l"(a), "l"(b)); return d;
}

// ---------------- math helpers ----------------
__device__ __forceinline__ float eluf(float z)      { return z > 0.f ? z : expm1f(z); }
__device__ __forceinline__ float sigmoidf_(float z) { return 1.f / (1.f + expf(-z)); }
__device__ __forceinline__ float softplusf_(float z){ return fmaxf(z, 0.f) + log1pf(expf(-fabsf(z))); }

// =====================================================================
// Kernel 0: build k-quad / k-pair weight layouts (fp32, exact)
// =====================================================================
__global__ void convert_kernel(const float* __restrict__ gru_W,
                               const float* __restrict__ img_W,
                               const float* __restrict__ obs_out_W,
                               const float* __restrict__ ims_W,
                               const float* __restrict__ obs_W)
{
    int i = blockIdx.x * blockDim.x + threadIdx.x;
    if (i < 102 * 600) {
        int k4 = i / 600, c = i % 600;
        float4 v = make_float4(0.f, 0.f, 0.f, 0.f);
        int k = 4 * k4;
        if (k     < 400) v.x = gru_W[(k)     * 600 + c];
        if (k + 1 < 400) v.y = gru_W[(k + 1) * 600 + c];
        if (k + 2 < 400) v.z = gru_W[(k + 2) * 600 + c];
        if (k + 3 < 400) v.w = gru_W[(k + 3) * 600 + c];
        g_Wq[i] = v;
    }
    if (i < 52 * 400) {
        int k4 = i / 400, c = i % 400;
        float4 v = make_float4(0.f, 0.f, 0.f, 0.f);
        int k = 4 * k4;
        float* pv = (float*)&v;
        for (int j = 0; j < 4; j++) {
            int kk = k + j;
            if (kk < 200)
                pv[j] = (c < 200) ? img_W[kk * 200 + c] : obs_out_W[kk * 200 + c - 200];
        }
        g_IOq[i] = v;
    }
    if (i < 104 * 120) {
        int k2 = i / 120, c = i % 120;
        float lo = 0.f, hi = 0.f;
        int k0 = 2 * k2, k1 = 2 * k2 + 1;
        if (k0 < 200) lo = (c < 60) ? ims_W[k0 * 60 + c] : obs_W[k0 * 60 + c - 60];
        if (k1 < 200) hi = (c < 60) ? ims_W[k1 * 60 + c] : obs_W[k1 * 60 + c - 60];
        g_EFp[i] = make_float2(lo, hi);
    }
}

// =====================================================================
// Kernel 1: precompute (fp32, unchanged)
// =====================================================================
#define PRE_ROWS 32
#define PRE_KC   256
#define PRE_PAD  36

__global__ void __launch_bounds__(224) precompute_kernel(
    const float* __restrict__ embed,
    const float* __restrict__ action,
    const float* __restrict__ obs_out_W,
    const float* __restrict__ obs_out_b,
    const float* __restrict__ inp_W,
    const float* __restrict__ inp_b)
{
    __shared__ __align__(16) float s_aT[PRE_KC * PRE_PAD];
    __shared__ float s_act[PRE_ROWS * NA];

    const int bt0 = blockIdx.x * PRE_ROWS;
    const int tid = threadIdx.x;
    const int j   = tid;

    ull acc[16];
    {
        float b = (j < NH) ? obs_out_b[j] : 0.f;
        ull bb = pack2(b, b);
#pragma unroll
        for (int i = 0; i < 16; i++) acc[i] = bb;
    }

    const float* W2 = obs_out_W + (size_t)ND * NH;

    for (int kc = 0; kc < NE; kc += PRE_KC) {
        __syncthreads();
        for (int idx = tid; idx < PRE_ROWS * PRE_KC; idx += blockDim.x) {
            int rr = idx / PRE_KC;
            int kk = idx % PRE_KC;
            s_aT[kk * PRE_PAD + rr] = embed[(size_t)(bt0 + rr) * NE + kc + kk];
        }
        __syncthreads();

        if (j < NH) {
#pragma unroll 2
            for (int kk = 0; kk < PRE_KC; kk++) {
                float w = W2[(size_t)(kc + kk) * NH + j];
                ull wv = pack2(w, w);
                const ulonglong2* ap = (const ulonglong2*)&s_aT[kk * PRE_PAD];
#pragma unroll
                for (int q = 0; q < 8; q++) {
                    ulonglong2 a = ap[q];
                    acc[2 * q]     = fma2(a.x, wv, acc[2 * q]);
                    acc[2 * q + 1] = fma2(a.y, wv, acc[2 * q + 1]);
                }
            }
        }
    }

    if (j < NH) {
#pragma unroll
        for (int q = 0; q < 8; q++) {
            float v0, v1, v2, v3;
            unpack2(acc[2 * q],     v0, v1);
            unpack2(acc[2 * q + 1], v2, v3);
            g_pre_obs[(size_t)(bt0 + 4 * q + 0) * NH + j] = v0;
            g_pre_obs[(size_t)(bt0 + 4 * q + 1) * NH + j] = v1;
            g_pre_obs[(size_t)(bt0 + 4 * q + 2) * NH + j] = v2;
            g_pre_obs[(size_t)(bt0 + 4 * q + 3) * NH + j] = v3;
        }
    }

    __syncthreads();
    for (int idx = tid; idx < PRE_ROWS * NA; idx += blockDim.x) {
        int rr = idx / NA, kk = idx % NA;
        s_act[idx] = action[(size_t)(bt0 + rr) * NA + kk];
    }
    __syncthreads();

    if (j < NH) {
        float ib = inp_b[j];
        float wA[NA];
#pragma unroll
        for (int k = 0; k < NA; k++) wA[k] = inp_W[(NS + k) * NH + j];
        for (int rr = 0; rr < PRE_ROWS; rr++) {
            float a = ib;
#pragma unroll
            for (int k = 0; k < NA; k++) a = fmaf(s_act[rr * NA + k], wA[k], a);
            g_pre_inp[(size_t)(bt0 + rr) * NH + j] = a;
        }
    }
}

// =====================================================================
// Kernel 2: scan. 128 CTAs x 4 rows, 640 threads.
// float4 k-quad weights, depth-2-quad prefetch, 4 accumulator chains,
// E/F k-split x4, software-pipelined pre_inp/pre_obs smem staging.
// =====================================================================
__global__ void __launch_bounds__(640) scan_kernel(
    const float* __restrict__ noise_prior,
    const float* __restrict__ noise_post,
    const float* __restrict__ inp_W,
    const float* __restrict__ gru_b,
    const float* __restrict__ img_out_b,
    const float* __restrict__ ims_b,
    const float* __restrict__ obs_b,
    float* __restrict__ out)
{
    __shared__ __align__(16) float s_xd[400 * R];   // x (0..199), deter (200..399)
    __shared__ __align__(16) float s_dn[200 * R];
    __shared__ __align__(16) float s_gr[200 * R];
    __shared__ __align__(16) float s_h [200 * R];
    __shared__ __align__(16) float s_ho[200 * R];
    __shared__ __align__(16) float s_pi [200 * R];  // staged pre_inp (current step)
    __shared__ __align__(16) float s_po2[200 * R];  // staged pre_obs (current step)
    __shared__ __align__(16) float s_stoch[32 * R];
    __shared__ __align__(16) ull   s_efp[480 * 2];  // E/F partials

    const int tid  = threadIdx.x;
    const int row0 = blockIdx.x * R;

    for (int i = tid; i < 400 * R; i += 640) s_xd[i] = 0.f;
    for (int i = tid; i < 32 * R;  i += 640) s_stoch[i] = 0.f;
    // prologue: stage step-0 pre_inp / pre_obs
    for (int i = tid; i < 200 * R; i += 640) {
        int r = i / 200, j = i % 200;
        size_t base = ((size_t)(row0 + r) * NT + 0) * NH + j;
        s_pi [j * R + r] = g_pre_inp[base];
        s_po2[j * R + r] = g_pre_obs[base];
    }
    __syncthreads();

    for (int t = 0; t < NT; t++) {
        // ===== A: x = elu(stoch @ inp_W[:30] + pre_inp)  (200 threads) =====
        if (tid < 200) {
            const int j = tid;
            ull a0 = *(const ull*)&s_pi[j * R];
            ull a1 = *(const ull*)&s_pi[j * R + 2];
            const ulonglong2* ap = (const ulonglong2*)s_stoch;
#pragma unroll
            for (int k = 0; k < NS; k++) {
                float w = inp_W[k * NH + j];
                ull wv = pack2(w, w);
                ulonglong2 v = ap[k];
                a0 = fma2(v.x, wv, a0);
                a1 = fma2(v.y, wv, a1);
            }
            float lo, hi;
            unpack2(a0, lo, hi); s_xd[j*R+0]=eluf(lo); s_xd[j*R+1]=eluf(hi);
            unpack2(a1, lo, hi); s_xd[j*R+2]=eluf(lo); s_xd[j*R+3]=eluf(hi);
        }
        __syncthreads();

        // ===== B: GRU dots (600 threads; col=tid; K=400 as 100 quads) =====
        if (tid < 600) {
            float b = gru_b[tid];
            ull a0 = pack2(b, b), a1 = a0;   // chain A (k%4==0)
            ull b0 = 0, b1 = 0;              // chain B
            ull c0 = 0, c1 = 0;              // chain C
            ull d0 = 0, d1 = 0;              // chain D
            const float4* wp = g_Wq + tid;
            const ulonglong2* ap = (const ulonglong2*)s_xd;
            float4 w0 = wp[0], w1 = wp[600];
            for (int q = 0; q < 100; q += 2) {
                float4 n0 = wp[(size_t)(q + 2) * 600];
                float4 n1 = wp[(size_t)(q + 3) * 600];
                ulonglong2 v; ull wv;
                v = ap[4*q+0]; wv = pack2(w0.x, w0.x); a0 = fma2(v.x, wv, a0); a1 = fma2(v.y, wv, a1);
                v = ap[4*q+1]; wv = pack2(w0.y, w0.y); b0 = fma2(v.x, wv, b0); b1 = fma2(v.y, wv, b1);
                v = ap[4*q+2]; wv = pack2(w0.z, w0.z); c0 = fma2(v.x, wv, c0); c1 = fma2(v.y, wv, c1);
                v = ap[4*q+3]; wv = pack2(w0.w, w0.w); d0 = fma2(v.x, wv, d0); d1 = fma2(v.y, wv, d1);
                v = ap[4*q+4]; wv = pack2(w1.x, w1.x); a0 = fma2(v.x, wv, a0); a1 = fma2(v.y, wv, a1);
                v = ap[4*q+5]; wv = pack2(w1.y, w1.y); b0 = fma2(v.x, wv, b0); b1 = fma2(v.y, wv, b1);
                v = ap[4*q+6]; wv = pack2(w1.z, w1.z); c0 = fma2(v.x, wv, c0); c1 = fma2(v.y, wv, c1);
                v = ap[4*q+7]; wv = pack2(w1.w, w1.w); d0 = fma2(v.x, wv, d0); d1 = fma2(v.y, wv, d1);
                w0 = n0; w1 = n1;
            }
            a0 = add2(add2(a0, b0), add2(c0, d0));
            a1 = add2(add2(a1, b1), add2(c1, d1));
            const int g = tid / 200, u = tid % 200;
            float* gbuf = (g == 0) ? s_gr : (g == 1) ? s_h : s_ho;
            float lo, hi;
            unpack2(a0, lo, hi); gbuf[u*R+0]=lo; gbuf[u*R+1]=hi;
            unpack2(a1, lo, hi); gbuf[u*R+2]=lo; gbuf[u*R+3]=hi;
        }
        __syncthreads();

        // ===== B2: gate combine -> deter_new (200 threads) =====
        if (tid < 200) {
            const int u = tid;
#pragma unroll
            for (int r = 0; r < R; r++) {
                float reset = sigmoidf_(s_gr[u * R + r]);
                float cand  = tanhf(reset * s_h[u * R + r]);
                float upd   = sigmoidf_(s_ho[u * R + r] - 1.0f);
                float dold  = s_xd[(200 + u) * R + r];
                float dn    = upd * cand + (1.f - upd) * dold;
                s_dn[u * R + r] = dn;
                s_xd[(200 + u) * R + r] = dn;
                out[(((size_t)(row0 + r)) * NT + t) * OUTC + 180 + u] = dn;
            }
        }
        __syncthreads();

        // ===== C/D: h / ho (400 threads; K=200 as 50 quads) =====
        if (tid < 400) {
            const int m = tid / 200;
            const int j = tid % 200;
            ull a0, a1;
            if (m == 0) {
                float b = img_out_b[j];
                a0 = pack2(b, b); a1 = a0;
            } else {
                a0 = *(const ull*)&s_po2[j * R];
                a1 = *(const ull*)&s_po2[j * R + 2];
            }
            ull b0 = 0, b1 = 0, c0 = 0, c1 = 0, d0 = 0, d1 = 0;
            const float4* wp = g_IOq + tid;
            const ulonglong2* ap = (const ulonglong2*)s_dn;
            float4 w0 = wp[0], w1 = wp[400];
            for (int q = 0; q < 50; q += 2) {
                float4 n0 = wp[(size_t)(q + 2) * 400];
                float4 n1 = wp[(size_t)(q + 3) * 400];
                ulonglong2 v; ull wv;
                v = ap[4*q+0]; wv = pack2(w0.x, w0.x); a0 = fma2(v.x, wv, a0); a1 = fma2(v.y, wv, a1);
                v = ap[4*q+1]; wv = pack2(w0.y, w0.y); b0 = fma2(v.x, wv, b0); b1 = fma2(v.y, wv, b1);
                v = ap[4*q+2]; wv = pack2(w0.z, w0.z); c0 = fma2(v.x, wv, c0); c1 = fma2(v.y, wv, c1);
                v = ap[4*q+3]; wv = pack2(w0.w, w0.w); d0 = fma2(v.x, wv, d0); d1 = fma2(v.y, wv, d1);
                v = ap[4*q+4]; wv = pack2(w1.x, w1.x); a0 = fma2(v.x, wv, a0); a1 = fma2(v.y, wv, a1);
                v = ap[4*q+5]; wv = pack2(w1.y, w1.y); b0 = fma2(v.x, wv, b0); b1 = fma2(v.y, wv, b1);
                v = ap[4*q+6]; wv = pack2(w1.z, w1.z); c0 = fma2(v.x, wv, c0); c1 = fma2(v.y, wv, c1);
                v = ap[4*q+7]; wv = pack2(w1.w, w1.w); d0 = fma2(v.x, wv, d0); d1 = fma2(v.y, wv, d1);
                w0 = n0; w1 = n1;
            }
            a0 = add2(add2(a0, b0), add2(c0, d0));
            a1 = add2(add2(a1, b1), add2(c1, d1));
            float* dst = (m == 0) ? s_h : s_ho;
            float lo, hi;
            unpack2(a0, lo, hi); dst[j*R+0]=eluf(lo); dst[j*R+1]=eluf(hi);
            unpack2(a1, lo, hi); dst[j*R+2]=eluf(lo); dst[j*R+3]=eluf(hi);
        }
        __syncthreads();

        // ===== E/F: stat layers, k-split x4 (480 thr) + stage t+1 pre (160 thr) =====
        if (tid < 480) {
            const int q = tid / 120;     // k-slice (50 k each)
            const int c = tid % 120;     // 0..59 ims, 60..119 obs
            const int m = c / 60;
            ull a0 = 0, a1 = 0;
            if (q == 0) {
                float b = (m == 0) ? ims_b[c] : obs_b[c - 60];
                a0 = pack2(b, b); a1 = a0;
            }
            const float2* wp = g_EFp + (q * 25) * 120 + c;
            const ulonglong2* ap = (const ulonglong2*)((m == 0) ? s_h : s_ho) + q * 50;
#pragma unroll
            for (int i = 0; i < 25; i++) {
                float2 w = wp[(size_t)i * 120];
                ull w0 = pack2(w.x, w.x), w1 = pack2(w.y, w.y);
                ulonglong2 vA = ap[2 * i], vB = ap[2 * i + 1];
                a0 = fma2(vA.x, w0, a0);  a1 = fma2(vA.y, w0, a1);
                a0 = fma2(vB.x, w1, a0);  a1 = fma2(vB.y, w1, a1);
            }
            s_efp[tid * 2]     = a0;
            s_efp[tid * 2 + 1] = a1;
        } else if (t + 1 < NT) {
            // stage next step's pre_inp / pre_obs
            for (int i = tid - 480; i < 200 * R; i += 160) {
                int r = i / 200, j = i % 200;
                size_t base = ((size_t)(row0 + r) * NT + (t + 1)) * NH + j;
                s_pi [j * R + r] = g_pre_inp[base];
                s_po2[j * R + r] = g_pre_obs[base];
            }
        }
        __syncthreads();

        // ===== finalize: combine E/F partials, sample, write, carry =====
        if (tid < NS) {                       // prior (ims)
            const int u = tid;
            ull m0 = 0, m1 = 0, s0 = 0, s1 = 0;
#pragma unroll
            for (int q = 0; q < 4; q++) {
                m0 = add2(m0, s_efp[(q * 120 + u) * 2]);
                m1 = add2(m1, s_efp[(q * 120 + u) * 2 + 1]);
                s0 = add2(s0, s_efp[(q * 120 + 30 + u) * 2]);
                s1 = add2(s1, s_efp[(q * 120 + 30 + u) * 2 + 1]);
            }
            float mm[R], ss[R];
            unpack2(m0, mm[0], mm[1]); unpack2(m1, mm[2], mm[3]);
            unpack2(s0, ss[0], ss[1]); unpack2(s1, ss[2], ss[3]);
#pragma unroll
            for (int r = 0; r < R; r++) {
                float sd = softplusf_(ss[r]) + 0.1f;
                size_t bt = ((size_t)(row0 + r)) * NT + t;
                float nz = noise_prior[bt * NS + u];
                size_t ob = bt * OUTC;
                out[ob + 120 + u] = mm[r];
                out[ob + 150 + u] = sd;
                out[ob +  90 + u] = mm[r] + sd * nz;
            }
        } else if (tid >= 32 && tid < 32 + NS) {  // posterior (obs)
            const int u = tid - 32;
            ull m0 = 0, m1 = 0, s0 = 0, s1 = 0;
#pragma unroll
            for (int q = 0; q < 4; q++) {
                m0 = add2(m0, s_efp[(q * 120 + 60 + u) * 2]);
                m1 = add2(m1, s_efp[(q * 120 + 60 + u) * 2 + 1]);
                s0 = add2(s0, s_efp[(q * 120 + 90 + u) * 2]);
                s1 = add2(s1, s_efp[(q * 120 + 90 + u) * 2 + 1]);
            }
            float mm[R], ss[R];
            unpack2(m0, mm[0], mm[1]); unpack2(m1, mm[2], mm[3]);
            unpack2(s0, ss[0], ss[1]); unpack2(s1, ss[2], ss[3]);
#pragma unroll
            for (int r = 0; r < R; r++) {
                float sd = softplusf_(ss[r]) + 0.1f;
                size_t bt = ((size_t)(row0 + r)) * NT + t;
                float nz = noise_post[bt * NS + u];
                float st = mm[r] + sd * nz;
                size_t ob = bt * OUTC;
                out[ob + 30 + u] = mm[r];
                out[ob + 60 + u] = sd;
                out[ob +  0 + u] = st;
                s_stoch[u * R + r] = st;
            }
        }
        __syncthreads();
    }
}

// =====================================================================
extern "C" void kernel_launch(void* const* d_in, const int* in_sizes, int n_in,
                              void* d_out, int out_size) {
    const float* embed       = (const float*)d_in[0];
    const float* action      = (const float*)d_in[1];
    const float* noise_prior = (const float*)d_in[2];
    const float* noise_post  = (const float*)d_in[3];
    const float* inp_W       = (const float*)d_in[4];
    const float* inp_b       = (const float*)d_in[5];
    const float* gru_W       = (const float*)d_in[6];
    const float* gru_b       = (const float*)d_in[7];
    const float* img_out_W   = (const float*)d_in[8];
    const float* img_out_b   = (const float*)d_in[9];
    const float* ims_W       = (const float*)d_in[10];
    const float* ims_b       = (const float*)d_in[11];
    const float* obs_out_W   = (const float*)d_in[12];
    const float* obs_out_b   = (const float*)d_in[13];
    const float* obs_W       = (const float*)d_in[14];
    const float* obs_b       = (const float*)d_in[15];
    float* out = (float*)d_out;

    convert_kernel<<<(102 * 600 + 255) / 256, 256>>>(gru_W, img_out_W, obs_out_W,
                                                     ims_W, obs_W);
    precompute_kernel<<<(NB * NT) / PRE_ROWS, 224>>>(embed, action, obs_out_W, obs_out_b,
                                                     inp_W, inp_b);
    scan_kernel<<<NCTA, 640>>>(noise_prior, noise_post, inp_W, gru_b,
                               img_out_b, ims_b, obs_b, out);
}

// round 10
// speedup vs baseline: 2.3103x; 1.0863x over previous
#include <cuda_runtime.h>
#include <cuda_fp16.h>
#include <math.h>

#define NB 512
#define NT 64
#define NS 30
#define ND 200
#define NH 200
#define NA 12
#define NE 1024
#define OUTC 380
#define R 4
#define NCTA (NB / R)   // 128

typedef unsigned long long ull;

// ---------------- device-global scratch (allocation-free rule) ----------------
// fp16 k-quad weights: one uint2 (8B) = 4 halves = W[4k4..4k4+3][c]; padded in k4.
__device__ __align__(16) uint2  g_Whq [102 * 600];  // GRU
__device__ __align__(16) uint2  g_IOhq[ 52 * 400];  // [img(200)|obs_out(200)]
__device__ __align__(16) float2 g_EFp [104 * 120];  // [ims(60)|obs(60)] fp32 k-pairs
__device__ float g_pre_inp[NB * NT * NH];
__device__ float g_pre_obs[NB * NT * NH];

// ---------------- packed f32x2 helpers ----------------
__device__ __forceinline__ ull pack2(float lo, float hi) {
    ull r; asm("mov.b64 %0, {%1, %2};" : "=l"(r) : "f"(lo), "f"(hi)); return r;
}
__device__ __forceinline__ void unpack2(ull v, float& lo, float& hi) {
    asm("mov.b64 {%0, %1}, %2;" : "=f"(lo), "=f"(hi) : "l"(v));
}
__device__ __forceinline__ ull fma2(ull a, ull b, ull c) {
    ull d; asm("fma.rn.f32x2 %0, %1, %2, %3;" : "=l"(d) : "l"(a), "l"(b), "l"(c)); return d;
}
__device__ __forceinline__ ull add2(ull a, ull b) {
    ull d; asm("add.rn.f32x2 %0, %1, %2;" : "=l"(d) : "l"(a), "l"(b)); return d;
}

// ---------------- math helpers ----------------
__device__ __forceinline__ float eluf(float z)      { return z > 0.f ? z : expm1f(z); }
__device__ __forceinline__ float sigmoidf_(float z) { return 1.f / (1.f + expf(-z)); }
__device__ __forceinline__ float softplusf_(float z){ return fmaxf(z, 0.f) + log1pf(expf(-fabsf(z))); }

// =====================================================================
// Kernel 0: build fp16 k-quad / fp32 k-pair weight layouts
// =====================================================================
__global__ void convert_kernel(const float* __restrict__ gru_W,
                               const float* __restrict__ img_W,
                               const float* __restrict__ obs_out_W,
                               const float* __restrict__ ims_W,
                               const float* __restrict__ obs_W)
{
    int i = blockIdx.x * blockDim.x + threadIdx.x;
    if (i < 102 * 600) {
        int k4 = i / 600, c = i % 600;
        int k = 4 * k4;
        float v0 = (k     < 400) ? gru_W[(k)     * 600 + c] : 0.f;
        float v1 = (k + 1 < 400) ? gru_W[(k + 1) * 600 + c] : 0.f;
        float v2 = (k + 2 < 400) ? gru_W[(k + 2) * 600 + c] : 0.f;
        float v3 = (k + 3 < 400) ? gru_W[(k + 3) * 600 + c] : 0.f;
        __half2 h01 = __floats2half2_rn(v0, v1);
        __half2 h23 = __floats2half2_rn(v2, v3);
        g_Whq[i] = make_uint2(*(unsigned*)&h01, *(unsigned*)&h23);
    }
    if (i < 52 * 400) {
        int k4 = i / 400, c = i % 400;
        int k = 4 * k4;
        float v[4];
        for (int j = 0; j < 4; j++) {
            int kk = k + j;
            v[j] = 0.f;
            if (kk < 200)
                v[j] = (c < 200) ? img_W[kk * 200 + c] : obs_out_W[kk * 200 + c - 200];
        }
        __half2 h01 = __floats2half2_rn(v[0], v[1]);
        __half2 h23 = __floats2half2_rn(v[2], v[3]);
        g_IOhq[i] = make_uint2(*(unsigned*)&h01, *(unsigned*)&h23);
    }
    if (i < 104 * 120) {
        int k2 = i / 120, c = i % 120;
        float lo = 0.f, hi = 0.f;
        int k0 = 2 * k2, k1 = 2 * k2 + 1;
        if (k0 < 200) lo = (c < 60) ? ims_W[k0 * 60 + c] : obs_W[k0 * 60 + c - 60];
        if (k1 < 200) hi = (c < 60) ? ims_W[k1 * 60 + c] : obs_W[k1 * 60 + c - 60];
        g_EFp[i] = make_float2(lo, hi);
    }
}

// =====================================================================
// Kernel 1: precompute (fp32, unchanged)
// =====================================================================
#define PRE_ROWS 32
#define PRE_KC   256
#define PRE_PAD  36

__global__ void __launch_bounds__(224) precompute_kernel(
    const float* __restrict__ embed,
    const float* __restrict__ action,
    const float* __restrict__ obs_out_W,
    const float* __restrict__ obs_out_b,
    const float* __restrict__ inp_W,
    const float* __restrict__ inp_b)
{
    __shared__ __align__(16) float s_aT[PRE_KC * PRE_PAD];
    __shared__ float s_act[PRE_ROWS * NA];

    const int bt0 = blockIdx.x * PRE_ROWS;
    const int tid = threadIdx.x;
    const int j   = tid;

    ull acc[16];
    {
        float b = (j < NH) ? obs_out_b[j] : 0.f;
        ull bb = pack2(b, b);
#pragma unroll
        for (int i = 0; i < 16; i++) acc[i] = bb;
    }

    const float* W2 = obs_out_W + (size_t)ND * NH;

    for (int kc = 0; kc < NE; kc += PRE_KC) {
        __syncthreads();
        for (int idx = tid; idx < PRE_ROWS * PRE_KC; idx += blockDim.x) {
            int rr = idx / PRE_KC;
            int kk = idx % PRE_KC;
            s_aT[kk * PRE_PAD + rr] = embed[(size_t)(bt0 + rr) * NE + kc + kk];
        }
        __syncthreads();

        if (j < NH) {
#pragma unroll 2
            for (int kk = 0; kk < PRE_KC; kk++) {
                float w = W2[(size_t)(kc + kk) * NH + j];
                ull wv = pack2(w, w);
                const ulonglong2* ap = (const ulonglong2*)&s_aT[kk * PRE_PAD];
#pragma unroll
                for (int q = 0; q < 8; q++) {
                    ulonglong2 a = ap[q];
                    acc[2 * q]     = fma2(a.x, wv, acc[2 * q]);
                    acc[2 * q + 1] = fma2(a.y, wv, acc[2 * q + 1]);
                }
            }
        }
    }

    if (j < NH) {
#pragma unroll
        for (int q = 0; q < 8; q++) {
            float v0, v1, v2, v3;
            unpack2(acc[2 * q],     v0, v1);
            unpack2(acc[2 * q + 1], v2, v3);
            g_pre_obs[(size_t)(bt0 + 4 * q + 0) * NH + j] = v0;
            g_pre_obs[(size_t)(bt0 + 4 * q + 1) * NH + j] = v1;
            g_pre_obs[(size_t)(bt0 + 4 * q + 2) * NH + j] = v2;
            g_pre_obs[(size_t)(bt0 + 4 * q + 3) * NH + j] = v3;
        }
    }

    __syncthreads();
    for (int idx = tid; idx < PRE_ROWS * NA; idx += blockDim.x) {
        int rr = idx / NA, kk = idx % NA;
        s_act[idx] = action[(size_t)(bt0 + rr) * NA + kk];
    }
    __syncthreads();

    if (j < NH) {
        float ib = inp_b[j];
        float wA[NA];
#pragma unroll
        for (int k = 0; k < NA; k++) wA[k] = inp_W[(NS + k) * NH + j];
        for (int rr = 0; rr < PRE_ROWS; rr++) {
            float a = ib;
#pragma unroll
            for (int k = 0; k < NA; k++) a = fmaf(s_act[rr * NA + k], wA[k], a);
            g_pre_inp[(size_t)(bt0 + rr) * NH + j] = a;
        }
    }
}

// =====================================================================
// Kernel 2: scan. 128 CTAs x 4 rows, 640 threads.
// fp16 k-quad weights (LDG.64 = 4 k), fp32 accumulate, depth-2-quad
// prefetch, 4 accumulator chains, E/F x4 split, pre-staging pipeline.
// =====================================================================
__global__ void __launch_bounds__(640) scan_kernel(
    const float* __restrict__ noise_prior,
    const float* __restrict__ noise_post,
    const float* __restrict__ inp_W,
    const float* __restrict__ gru_b,
    const float* __restrict__ img_out_b,
    const float* __restrict__ ims_b,
    const float* __restrict__ obs_b,
    float* __restrict__ out)
{
    __shared__ __align__(16) float s_xd[400 * R];   // x (0..199), deter (200..399)
    __shared__ __align__(16) float s_dn[200 * R];
    __shared__ __align__(16) float s_gr[200 * R];
    __shared__ __align__(16) float s_h [200 * R];
    __shared__ __align__(16) float s_ho[200 * R];
    __shared__ __align__(16) float s_pi [200 * R];
    __shared__ __align__(16) float s_po2[200 * R];
    __shared__ __align__(16) float s_stoch[32 * R];
    __shared__ __align__(16) ull   s_efp[480 * 2];

    const int tid  = threadIdx.x;
    const int row0 = blockIdx.x * R;

    for (int i = tid; i < 400 * R; i += 640) s_xd[i] = 0.f;
    for (int i = tid; i < 32 * R;  i += 640) s_stoch[i] = 0.f;
    for (int i = tid; i < 200 * R; i += 640) {
        int r = i / 200, j = i % 200;
        size_t base = ((size_t)(row0 + r) * NT + 0) * NH + j;
        s_pi [j * R + r] = g_pre_inp[base];
        s_po2[j * R + r] = g_pre_obs[base];
    }
    __syncthreads();

    for (int t = 0; t < NT; t++) {
        // ===== A: x = elu(stoch @ inp_W[:30] + pre_inp)  (200 threads) =====
        if (tid < 200) {
            const int j = tid;
            ull a0 = *(const ull*)&s_pi[j * R];
            ull a1 = *(const ull*)&s_pi[j * R + 2];
            const ulonglong2* ap = (const ulonglong2*)s_stoch;
#pragma unroll
            for (int k = 0; k < NS; k++) {
                float w = inp_W[k * NH + j];
                ull wv = pack2(w, w);
                ulonglong2 v = ap[k];
                a0 = fma2(v.x, wv, a0);
                a1 = fma2(v.y, wv, a1);
            }
            float lo, hi;
            unpack2(a0, lo, hi); s_xd[j*R+0]=eluf(lo); s_xd[j*R+1]=eluf(hi);
            unpack2(a1, lo, hi); s_xd[j*R+2]=eluf(lo); s_xd[j*R+3]=eluf(hi);
        }
        __syncthreads();

        // ===== B: GRU dots (600 threads; col=tid; K=400 as 100 fp16 quads) =====
        if (tid < 600) {
            float b = gru_b[tid];
            ull a0 = pack2(b, b), a1 = a0;
            ull b0 = 0, b1 = 0, c0 = 0, c1 = 0, d0 = 0, d1 = 0;
            const uint2* wp = g_Whq + tid;
            const ulonglong2* ap = (const ulonglong2*)s_xd;
            uint2 w0 = wp[0], w1 = wp[600];
            for (int q = 0; q < 100; q += 2) {
                uint2 n0 = wp[(size_t)(q + 2) * 600];
                uint2 n1 = wp[(size_t)(q + 3) * 600];
                float2 f01 = __half22float2(*(const __half2*)&w0.x);
                float2 f23 = __half22float2(*(const __half2*)&w0.y);
                ulonglong2 v; ull wv;
                v = ap[4*q+0]; wv = pack2(f01.x, f01.x); a0 = fma2(v.x, wv, a0); a1 = fma2(v.y, wv, a1);
                v = ap[4*q+1]; wv = pack2(f01.y, f01.y); b0 = fma2(v.x, wv, b0); b1 = fma2(v.y, wv, b1);
                v = ap[4*q+2]; wv = pack2(f23.x, f23.x); c0 = fma2(v.x, wv, c0); c1 = fma2(v.y, wv, c1);
                v = ap[4*q+3]; wv = pack2(f23.y, f23.y); d0 = fma2(v.x, wv, d0); d1 = fma2(v.y, wv, d1);
                f01 = __half22float2(*(const __half2*)&w1.x);
                f23 = __half22float2(*(const __half2*)&w1.y);
                v = ap[4*q+4]; wv = pack2(f01.x, f01.x); a0 = fma2(v.x, wv, a0); a1 = fma2(v.y, wv, a1);
                v = ap[4*q+5]; wv = pack2(f01.y, f01.y); b0 = fma2(v.x, wv, b0); b1 = fma2(v.y, wv, b1);
                v = ap[4*q+6]; wv = pack2(f23.x, f23.x); c0 = fma2(v.x, wv, c0); c1 = fma2(v.y, wv, c1);
                v = ap[4*q+7]; wv = pack2(f23.y, f23.y); d0 = fma2(v.x, wv, d0); d1 = fma2(v.y, wv, d1);
                w0 = n0; w1 = n1;
            }
            a0 = add2(add2(a0, b0), add2(c0, d0));
            a1 = add2(add2(a1, b1), add2(c1, d1));
            const int g = tid / 200, u = tid % 200;
            float* gbuf = (g == 0) ? s_gr : (g == 1) ? s_h : s_ho;
            float lo, hi;
            unpack2(a0, lo, hi); gbuf[u*R+0]=lo; gbuf[u*R+1]=hi;
            unpack2(a1, lo, hi); gbuf[u*R+2]=lo; gbuf[u*R+3]=hi;
        }
        __syncthreads();

        // ===== B2: gate combine -> deter_new (200 threads) =====
        if (tid < 200) {
            const int u = tid;
#pragma unroll
            for (int r = 0; r < R; r++) {
                float reset = sigmoidf_(s_gr[u * R + r]);
                float cand  = tanhf(reset * s_h[u * R + r]);
                float upd   = sigmoidf_(s_ho[u * R + r] - 1.0f);
                float dold  = s_xd[(200 + u) * R + r];
                float dn    = upd * cand + (1.f - upd) * dold;
                s_dn[u * R + r] = dn;
                s_xd[(200 + u) * R + r] = dn;
                out[(((size_t)(row0 + r)) * NT + t) * OUTC + 180 + u] = dn;
            }
        }
        __syncthreads();

        // ===== C/D: h / ho (400 threads; K=200 as 50 fp16 quads) =====
        if (tid < 400) {
            const int m = tid / 200;
            const int j = tid % 200;
            ull a0, a1;
            if (m == 0) {
                float b = img_out_b[j];
                a0 = pack2(b, b); a1 = a0;
            } else {
                a0 = *(const ull*)&s_po2[j * R];
                a1 = *(const ull*)&s_po2[j * R + 2];
            }
            ull b0 = 0, b1 = 0, c0 = 0, c1 = 0, d0 = 0, d1 = 0;
            const uint2* wp = g_IOhq + tid;
            const ulonglong2* ap = (const ulonglong2*)s_dn;
            uint2 w0 = wp[0], w1 = wp[400];
            for (int q = 0; q < 50; q += 2) {
                uint2 n0 = wp[(size_t)(q + 2) * 400];
                uint2 n1 = wp[(size_t)(q + 3) * 400];
                float2 f01 = __half22float2(*(const __half2*)&w0.x);
                float2 f23 = __half22float2(*(const __half2*)&w0.y);
                ulonglong2 v; ull wv;
                v = ap[4*q+0]; wv = pack2(f01.x, f01.x); a0 = fma2(v.x, wv, a0); a1 = fma2(v.y, wv, a1);
                v = ap[4*q+1]; wv = pack2(f01.y, f01.y); b0 = fma2(v.x, wv, b0); b1 = fma2(v.y, wv, b1);
                v = ap[4*q+2]; wv = pack2(f23.x, f23.x); c0 = fma2(v.x, wv, c0); c1 = fma2(v.y, wv, c1);
                v = ap[4*q+3]; wv = pack2(f23.y, f23.y); d0 = fma2(v.x, wv, d0); d1 = fma2(v.y, wv, d1);
                f01 = __half22float2(*(const __half2*)&w1.x);
                f23 = __half22float2(*(const __half2*)&w1.y);
                v = ap[4*q+4]; wv = pack2(f01.x, f01.x); a0 = fma2(v.x, wv, a0); a1 = fma2(v.y, wv, a1);
                v = ap[4*q+5]; wv = pack2(f01.y, f01.y); b0 = fma2(v.x, wv, b0); b1 = fma2(v.y, wv, b1);
                v = ap[4*q+6]; wv = pack2(f23.x, f23.x); c0 = fma2(v.x, wv, c0); c1 = fma2(v.y, wv, c1);
                v = ap[4*q+7]; wv = pack2(f23.y, f23.y); d0 = fma2(v.x, wv, d0); d1 = fma2(v.y, wv, d1);
                w0 = n0; w1 = n1;
            }
            a0 = add2(add2(a0, b0), add2(c0, d0));
            a1 = add2(add2(a1, b1), add2(c1, d1));
            float* dst = (m == 0) ? s_h : s_ho;
            float lo, hi;
            unpack2(a0, lo, hi); dst[j*R+0]=eluf(lo); dst[j*R+1]=eluf(hi);
            unpack2(a1, lo, hi); dst[j*R+2]=eluf(lo); dst[j*R+3]=eluf(hi);
        }
        __syncthreads();

        // ===== E/F: stat layers x4 split (480 thr) + stage t+1 pre (160 thr) =====
        if (tid < 480) {
            const int q = tid / 120;
            const int c = tid % 120;
            const int m = c / 60;
            ull a0 = 0, a1 = 0;
            if (q == 0) {
                float b = (m == 0) ? ims_b[c] : obs_b[c - 60];
                a0 = pack2(b, b); a1 = a0;
            }
            const float2* wp = g_EFp + (q * 25) * 120 + c;
            const ulonglong2* ap = (const ulonglong2*)((m == 0) ? s_h : s_ho) + q * 50;
#pragma unroll
            for (int i = 0; i < 25; i++) {
                float2 w = wp[(size_t)i * 120];
                ull w0 = pack2(w.x, w.x), w1 = pack2(w.y, w.y);
                ulonglong2 vA = ap[2 * i], vB = ap[2 * i + 1];
                a0 = fma2(vA.x, w0, a0);  a1 = fma2(vA.y, w0, a1);
                a0 = fma2(vB.x, w1, a0);  a1 = fma2(vB.y, w1, a1);
            }
            s_efp[tid * 2]     = a0;
            s_efp[tid * 2 + 1] = a1;
        } else if (t + 1 < NT) {
            for (int i = tid - 480; i < 200 * R; i += 160) {
                int r = i / 200, j = i % 200;
                size_t base = ((size_t)(row0 + r) * NT + (t + 1)) * NH + j;
                s_pi [j * R + r] = g_pre_inp[base];
                s_po2[j * R + r] = g_pre_obs[base];
            }
        }
        __syncthreads();

        // ===== finalize: combine E/F partials, sample, write, carry =====
        if (tid < NS) {
            const int u = tid;
            ull m0 = 0, m1 = 0, s0 = 0, s1 = 0;
#pragma unroll
            for (int q = 0; q < 4; q++) {
                m0 = add2(m0, s_efp[(q * 120 + u) * 2]);
                m1 = add2(m1, s_efp[(q * 120 + u) * 2 + 1]);
                s0 = add2(s0, s_efp[(q * 120 + 30 + u) * 2]);
                s1 = add2(s1, s_efp[(q * 120 + 30 + u) * 2 + 1]);
            }
            float mm[R], ss[R];
            unpack2(m0, mm[0], mm[1]); unpack2(m1, mm[2], mm[3]);
            unpack2(s0, ss[0], ss[1]); unpack2(s1, ss[2], ss[3]);
#pragma unroll
            for (int r = 0; r < R; r++) {
                float sd = softplusf_(ss[r]) + 0.1f;
                size_t bt = ((size_t)(row0 + r)) * NT + t;
                float nz = noise_prior[bt * NS + u];
                size_t ob = bt * OUTC;
                out[ob + 120 + u] = mm[r];
                out[ob + 150 + u] = sd;
                out[ob +  90 + u] = mm[r] + sd * nz;
            }
        } else if (tid >= 32 && tid < 32 + NS) {
            const int u = tid - 32;
            ull m0 = 0, m1 = 0, s0 = 0, s1 = 0;
#pragma unroll
            for (int q = 0; q < 4; q++) {
                m0 = add2(m0, s_efp[(q * 120 + 60 + u) * 2]);
                m1 = add2(m1, s_efp[(q * 120 + 60 + u) * 2 + 1]);
                s0 = add2(s0, s_efp[(q * 120 + 90 + u) * 2]);
                s1 = add2(s1, s_efp[(q * 120 + 90 + u) * 2 + 1]);
            }
            float mm[R], ss[R];
            unpack2(m0, mm[0], mm[1]); unpack2(m1, mm[2], mm[3]);
            unpack2(s0, ss[0], ss[1]); unpack2(s1, ss[2], ss[3]);
#pragma unroll
            for (int r = 0; r < R; r++) {
                float sd = softplusf_(ss[r]) + 0.1f;
                size_t bt = ((size_t)(row0 + r)) * NT + t;
                float nz = noise_post[bt * NS + u];
                float st = mm[r] + sd * nz;
                size_t ob = bt * OUTC;
                out[ob + 30 + u] = mm[r];
                out[ob + 60 + u] = sd;
                out[ob +  0 + u] = st;
                s_stoch[u * R + r] = st;
            }
        }
        __syncthreads();
    }
}

// =====================================================================
extern "C" void kernel_launch(void* const* d_in, const int* in_sizes, int n_in,
                              void* d_out, int out_size) {
    const float* embed       = (const float*)d_in[0];
    const float* action      = (const float*)d_in[1];
    const float* noise_prior = (const float*)d_in[2];
    const float* noise_post  = (const float*)d_in[3];
    const float* inp_W       = (const float*)d_in[4];
    const float* inp_b       = (const float*)d_in[5];
    const float* gru_W       = (const float*)d_in[6];
    const float* gru_b       = (const float*)d_in[7];
    const float* img_out_W   = (const float*)d_in[8];
    const float* img_out_b   = (const float*)d_in[9];
    const float* ims_W       = (const float*)d_in[10];
    const float* ims_b       = (const float*)d_in[11];
    const float* obs_out_W   = (const float*)d_in[12];
    const float* obs_out_b   = (const float*)d_in[13];
    const float* obs_W       = (const float*)d_in[14];
    const float* obs_b       = (const float*)d_in[15];
    float* out = (float*)d_out;

    convert_kernel<<<(102 * 600 + 255) / 256, 256>>>(gru_W, img_out_W, obs_out_W,
                                                     ims_W, obs_W);
    precompute_kernel<<<(NB * NT) / PRE_ROWS, 224>>>(embed, action, obs_out_W, obs_out_b,
                                                     inp_W, inp_b);
    scan_kernel<<<NCTA, 640>>>(noise_prior, noise_post, inp_W, gru_b,
                               img_out_b, ims_b, obs_b, out);
}